// round 8
// baseline (speedup 1.0000x reference)
#include <cuda_runtime.h>
#include <cstdint>
#include <cstddef>

#define Bz 32
#define Dd 1024
#define Ff 512
#define Hh 16
#define Oo 4
#define FC 4096
#define CH 16           // wsum chunks
#define FL 32           // frames per chunk

// Deterministic scratch (no device allocation allowed)
__device__ float g_logits[Oo * Bz * Hh * Ff];        // [o][b][h][f]  4 MB
__device__ float g_hcat_part[CH * Bz * FC];          // [chunk][b][o*1024+d] 8 MB
__device__ float g_hidden_part[16 * Bz * FC];        // [kblk][b][j]

// ---------------------------------------------------------------------------
// Kernel A: logits[o,b,h,f] = (x[f,b,h,:] . q[o,h,:]) / 8, masked to -50
// ---------------------------------------------------------------------------
__global__ void k_logits(const float* __restrict__ x, const int* __restrict__ nfp,
                         const float* __restrict__ q) {
    extern __shared__ float sm[];
    float* qs = sm;                 // 64 * 67
    float* xs = sm + 64 * 67;       // 8 * (16*66) = 8 * 1056
    int b  = blockIdx.x;
    int f0 = blockIdx.y * 8;
    int t  = threadIdx.x;
    int nf = nfp[b];

    for (int i = t; i < 64 * 64; i += 512)
        qs[(i >> 6) * 67 + (i & 63)] = q[i];

    for (int i = t; i < 8 * 512; i += 512) {
        int ff = i >> 9, j2 = i & 511;
        if (f0 + ff < nf) {
            int j = j2 * 2;
            float2 v = *(const float2*)&x[((size_t)(f0 + ff) * Bz + b) * Dd + j];
            *(float2*)&xs[ff * 1056 + (j >> 6) * 66 + (j & 63)] = v;
        }
    }
    __syncthreads();

    int fl = t >> 6;
    int oh = t & 63;
    int o = oh >> 4, h = oh & 15;
    int f = f0 + fl;

    float acc;
    if (f >= nf) {
        acc = -50.0f;
    } else {
        const float* xp = xs + fl * 1056 + h * 66;
        const float* qp = qs + oh * 67;
        float a = 0.f;
#pragma unroll
        for (int s = 0; s < 64; s++) a = fmaf(xp[s], qp[s], a);
        acc = a * 0.125f;
    }
    g_logits[((size_t)(o * Bz + b) * Hh + h) * Ff + f] = acc;
}

// ---------------------------------------------------------------------------
// Kernel B: softmax over f, writes attn in reference layout [o][f][b][h].
// ---------------------------------------------------------------------------
__global__ void k_softmax(float* __restrict__ attn) {
    int ob = blockIdx.x;
    int o = ob >> 5, b = ob & 31;
    int t = threadIdx.x;           // 256
    int w = t >> 5, lane = t & 31;

    __shared__ float ls[Hh * Ff];  // 32 KB
    __shared__ float si[Hh];

    const float* src = g_logits + (size_t)(o * Bz + b) * Hh * Ff;
    for (int i = t; i < Hh * Ff; i += 256) ls[i] = src[i];
    __syncthreads();

    for (int hh = w; hh < Hh; hh += 8) {
        float* lp = ls + hh * Ff;
        float m = -1e30f;
        for (int k = lane; k < Ff; k += 32) m = fmaxf(m, lp[k]);
#pragma unroll
        for (int off = 16; off; off >>= 1)
            m = fmaxf(m, __shfl_xor_sync(0xffffffffu, m, off));
        float s = 0.f;
        for (int k = lane; k < Ff; k += 32) {
            float e = __expf(lp[k] - m);
            lp[k] = e;
            s += e;
        }
#pragma unroll
        for (int off = 16; off; off >>= 1)
            s += __shfl_xor_sync(0xffffffffu, s, off);
        if (lane == 0) si[hh] = 1.0f / s;
    }
    __syncthreads();

    float* dst = attn + (size_t)o * Ff * Bz * Hh + b * Hh;
    for (int i = t; i < Hh * Ff; i += 256) {
        int f = i >> 4, hh = i & 15;
        dst[(size_t)f * (Bz * Hh) + hh] = ls[hh * Ff + f] * si[hh];
    }
}

// ---------------------------------------------------------------------------
// Kernel C: partial weighted sums, 16 chunks x 32 frames (MLP 8 via unroll).
// ---------------------------------------------------------------------------
__global__ void k_wsum(const float* __restrict__ x, const int* __restrict__ nfp,
                       const float* __restrict__ attn) {
    int b = blockIdx.x;
    int c = blockIdx.y;
    int f0 = c * FL;
    int nf = nfp[b];
    int d = threadIdx.x;
    int h = d >> 6;

    __shared__ float as[Oo * FL * Hh];   // [o][fl][h] 8 KB
    float a0 = 0.f, a1 = 0.f, a2 = 0.f, a3 = 0.f;

    if (f0 < nf) {
        for (int i = d; i < Oo * FL * Hh; i += 1024) {
            int o = i >> 9, r = i & 511;   // r = fl*16 + h
            as[i] = attn[(size_t)o * (Ff * Bz * Hh) +
                         (size_t)(f0 + (r >> 4)) * (Bz * Hh) + b * Hh + (r & 15)];
        }
        __syncthreads();
        int fe = min(FL, nf - f0);
        const float* xp = x + ((size_t)f0 * Bz + b) * Dd + d;
        if (fe == FL) {
#pragma unroll 8
            for (int fl = 0; fl < FL; fl++) {
                float xv = xp[(size_t)fl * (Bz * Dd)];
                int ai = fl * 16 + h;
                a0 = fmaf(xv, as[ai],       a0);
                a1 = fmaf(xv, as[512 + ai], a1);
                a2 = fmaf(xv, as[1024 + ai], a2);
                a3 = fmaf(xv, as[1536 + ai], a3);
            }
        } else {
            for (int fl = 0; fl < fe; fl++) {
                float xv = xp[(size_t)fl * (Bz * Dd)];
                int ai = fl * 16 + h;
                a0 = fmaf(xv, as[ai],       a0);
                a1 = fmaf(xv, as[512 + ai], a1);
                a2 = fmaf(xv, as[1024 + ai], a2);
                a3 = fmaf(xv, as[1536 + ai], a3);
            }
        }
    }
    float* p = g_hcat_part + ((size_t)c * Bz + b) * FC + d;
    p[0] = a0; p[1024] = a1; p[2048] = a2; p[3072] = a3;
}

// ---------------------------------------------------------------------------
// Kernel D: hidden_part[kb][b][j] = sum_k hcat[b][k] * W1[k][j]
// Chunk-partial summation folded into smem staging (L2-resident partials).
// Scalar FFMA inner loop, 32 accumulators.
// launch_bounds(128,5): 20 warps/SM (was 13 @ occ 20.7%, issue 32.6%) —
// dependency-stall coverage is the limiter, not the FFMA pipe.
// ---------------------------------------------------------------------------
__global__ void __launch_bounds__(128, 5) k_gemm1(const float* __restrict__ W1) {
    int t = threadIdx.x;                  // 128
    int j = blockIdx.x * 128 + t;
    int k0 = blockIdx.y * 256;

    __shared__ float hs[128 * 36];        // 18 KB, rows 16B-aligned
    float acc[32];
#pragma unroll
    for (int i = 0; i < 32; i++) acc[i] = 0.f;

    for (int kt = 0; kt < 2; kt++) {
        int kb = k0 + kt * 128;
        __syncthreads();
        for (int i = t; i < 32 * 128; i += 128) {
            int b = i >> 7, kl = i & 127;
            const float* pp = g_hcat_part + (size_t)b * FC + kb + kl;
            float s = 0.f;
#pragma unroll
            for (int c = 0; c < CH; c++) s += pp[(size_t)c * (Bz * FC)];
            hs[kl * 36 + b] = s;
        }
        __syncthreads();
        const float* wp = W1 + (size_t)kb * FC + j;
#pragma unroll 4
        for (int kl = 0; kl < 128; kl++) {
            float w = wp[(size_t)kl * FC];
            const float4* hp = (const float4*)&hs[kl * 36];
#pragma unroll
            for (int q4 = 0; q4 < 8; q4++) {
                float4 hv = hp[q4];
                acc[q4 * 4 + 0] = fmaf(hv.x, w, acc[q4 * 4 + 0]);
                acc[q4 * 4 + 1] = fmaf(hv.y, w, acc[q4 * 4 + 1]);
                acc[q4 * 4 + 2] = fmaf(hv.z, w, acc[q4 * 4 + 2]);
                acc[q4 * 4 + 3] = fmaf(hv.w, w, acc[q4 * 4 + 3]);
            }
        }
    }
    float* dst = g_hidden_part + (size_t)blockIdx.y * (Bz * FC) + j;
#pragma unroll
    for (int b = 0; b < 32; b++) dst[(size_t)b * FC] = acc[b];
}

// ---------------------------------------------------------------------------
// Kernel E: out[b][n] = b2[n] + sum_j relu(sum_kb hidden_part + b1[j]) * W2[j][n]
// float4 over j: 16 independent LDG.128 per j4 -> high MLP.
// ---------------------------------------------------------------------------
__global__ void k_out(const float* __restrict__ b1, const float* __restrict__ W2,
                      const float* __restrict__ b2, float* __restrict__ out) {
    int b = blockIdx.x;
    int t = threadIdx.x;   // 256
    float a0 = 0.f, a1 = 0.f, a2 = 0.f, a3 = 0.f;

#pragma unroll
    for (int p = 0; p < 4; p++) {
        int j = (t + p * 256) * 4;
        float4 hv = *(const float4*)(b1 + j);
#pragma unroll
        for (int kb = 0; kb < 16; kb++) {
            float4 v = *(const float4*)&g_hidden_part[((size_t)kb * Bz + b) * FC + j];
            hv.x += v.x; hv.y += v.y; hv.z += v.z; hv.w += v.w;
        }
        hv.x = fmaxf(hv.x, 0.f); hv.y = fmaxf(hv.y, 0.f);
        hv.z = fmaxf(hv.z, 0.f); hv.w = fmaxf(hv.w, 0.f);
#pragma unroll
        for (int e = 0; e < 4; e++) {
            float h = e == 0 ? hv.x : e == 1 ? hv.y : e == 2 ? hv.z : hv.w;
            float4 w = *(const float4*)(W2 + (size_t)(j + e) * 4);
            a0 = fmaf(h, w.x, a0);
            a1 = fmaf(h, w.y, a1);
            a2 = fmaf(h, w.z, a2);
            a3 = fmaf(h, w.w, a3);
        }
    }
#pragma unroll
    for (int off = 16; off; off >>= 1) {
        a0 += __shfl_xor_sync(0xffffffffu, a0, off);
        a1 += __shfl_xor_sync(0xffffffffu, a1, off);
        a2 += __shfl_xor_sync(0xffffffffu, a2, off);
        a3 += __shfl_xor_sync(0xffffffffu, a3, off);
    }
    __shared__ float s[8][4];
    if ((t & 31) == 0) {
        int w = t >> 5;
        s[w][0] = a0; s[w][1] = a1; s[w][2] = a2; s[w][3] = a3;
    }
    __syncthreads();
    if (t < 4) {
        float r = 0.f;
#pragma unroll
        for (int w = 0; w < 8; w++) r += s[w][t];
        out[b * 4 + t] = r + b2[t];
    }
}

// ---------------------------------------------------------------------------
extern "C" void kernel_launch(void* const* d_in, const int* in_sizes, int n_in,
                              void* d_out, int out_size) {
    const float* x  = (const float*)d_in[0];
    const int*   nf = (const int*)  d_in[1];
    const float* q  = (const float*)d_in[2];
    const float* W1 = (const float*)d_in[3];
    const float* b1 = (const float*)d_in[4];
    const float* W2 = (const float*)d_in[5];
    const float* b2 = (const float*)d_in[6];

    float* out_p  = (float*)d_out;              // (B, 4) = 128 floats
    float* attn_p = out_p + Bz * Oo;            // (O, F, B, H) = 1,048,576 floats

    const int smemA = (64 * 67 + 8 * 1056) * 4; // 50944 B > 48 KB default
    cudaFuncSetAttribute(k_logits, cudaFuncAttributeMaxDynamicSharedMemorySize, smemA);

    dim3 gA(Bz, Ff / 8);
    k_logits<<<gA, 512, smemA>>>(x, nf, q);

    k_softmax<<<Oo * Bz, 256>>>(attn_p);

    dim3 gC(Bz, CH);
    k_wsum<<<gC, 1024>>>(x, nf, attn_p);

    dim3 gD(FC / 128, 16);
    k_gemm1<<<gD, 128>>>(W1);                   // 4th launch -> ncu capture slot

    k_out<<<Bz, 256>>>(b1, W2, b2, out_p);
}

// round 9
// speedup vs baseline: 1.0835x; 1.0835x over previous
#include <cuda_runtime.h>
#include <cstdint>
#include <cstddef>

#define Bz 32
#define Dd 1024
#define Ff 512
#define Hh 16
#define Oo 4
#define FC 4096
#define CH 16           // wsum chunks
#define FL 32           // frames per chunk
#define NK 32           // gemm1 k-splits

// Deterministic scratch (no device allocation allowed)
__device__ float g_logits[Oo * Bz * Hh * Ff];        // [o][b][h][f]  4 MB
__device__ float g_hcat_part[CH * Bz * FC];          // [chunk][b][o*1024+d] 8 MB
__device__ float g_hcat[Bz * FC];                    // [b][o*1024+d]  512 KB
__device__ float g_hidden_part[NK * Bz * FC];        // [kblk][b][j]  16 MB

// ---------------------------------------------------------------------------
// Kernel A: logits[o,b,h,f] = (x[f,b,h,:] . q[o,h,:]) / 8, masked to -50
// ---------------------------------------------------------------------------
__global__ void k_logits(const float* __restrict__ x, const int* __restrict__ nfp,
                         const float* __restrict__ q) {
    extern __shared__ float sm[];
    float* qs = sm;                 // 64 * 67
    float* xs = sm + 64 * 67;       // 8 * (16*66) = 8 * 1056
    int b  = blockIdx.x;
    int f0 = blockIdx.y * 8;
    int t  = threadIdx.x;
    int nf = nfp[b];

    for (int i = t; i < 64 * 64; i += 512)
        qs[(i >> 6) * 67 + (i & 63)] = q[i];

    for (int i = t; i < 8 * 512; i += 512) {
        int ff = i >> 9, j2 = i & 511;
        if (f0 + ff < nf) {
            int j = j2 * 2;
            float2 v = *(const float2*)&x[((size_t)(f0 + ff) * Bz + b) * Dd + j];
            *(float2*)&xs[ff * 1056 + (j >> 6) * 66 + (j & 63)] = v;
        }
    }
    __syncthreads();

    int fl = t >> 6;
    int oh = t & 63;
    int o = oh >> 4, h = oh & 15;
    int f = f0 + fl;

    float acc;
    if (f >= nf) {
        acc = -50.0f;
    } else {
        const float* xp = xs + fl * 1056 + h * 66;
        const float* qp = qs + oh * 67;
        float a = 0.f;
#pragma unroll
        for (int s = 0; s < 64; s++) a = fmaf(xp[s], qp[s], a);
        acc = a * 0.125f;
    }
    g_logits[((size_t)(o * Bz + b) * Hh + h) * Ff + f] = acc;
}

// ---------------------------------------------------------------------------
// Kernel B: softmax over f, writes attn in reference layout [o][f][b][h].
// ---------------------------------------------------------------------------
__global__ void k_softmax(float* __restrict__ attn) {
    int ob = blockIdx.x;
    int o = ob >> 5, b = ob & 31;
    int t = threadIdx.x;           // 256
    int w = t >> 5, lane = t & 31;

    __shared__ float ls[Hh * Ff];  // 32 KB
    __shared__ float si[Hh];

    const float* src = g_logits + (size_t)(o * Bz + b) * Hh * Ff;
    for (int i = t; i < Hh * Ff; i += 256) ls[i] = src[i];
    __syncthreads();

    for (int hh = w; hh < Hh; hh += 8) {
        float* lp = ls + hh * Ff;
        float m = -1e30f;
        for (int k = lane; k < Ff; k += 32) m = fmaxf(m, lp[k]);
#pragma unroll
        for (int off = 16; off; off >>= 1)
            m = fmaxf(m, __shfl_xor_sync(0xffffffffu, m, off));
        float s = 0.f;
        for (int k = lane; k < Ff; k += 32) {
            float e = __expf(lp[k] - m);
            lp[k] = e;
            s += e;
        }
#pragma unroll
        for (int off = 16; off; off >>= 1)
            s += __shfl_xor_sync(0xffffffffu, s, off);
        if (lane == 0) si[hh] = 1.0f / s;
    }
    __syncthreads();

    float* dst = attn + (size_t)o * Ff * Bz * Hh + b * Hh;
    for (int i = t; i < Hh * Ff; i += 256) {
        int f = i >> 4, hh = i & 15;
        dst[(size_t)f * (Bz * Hh) + hh] = ls[hh * Ff + f] * si[hh];
    }
}

// ---------------------------------------------------------------------------
// Kernel C: partial weighted sums, 16 chunks x 32 frames (MLP 8 via unroll).
// ---------------------------------------------------------------------------
__global__ void k_wsum(const float* __restrict__ x, const int* __restrict__ nfp,
                       const float* __restrict__ attn) {
    int b = blockIdx.x;
    int c = blockIdx.y;
    int f0 = c * FL;
    int nf = nfp[b];
    int d = threadIdx.x;
    int h = d >> 6;

    __shared__ float as[Oo * FL * Hh];   // [o][fl][h] 8 KB
    float a0 = 0.f, a1 = 0.f, a2 = 0.f, a3 = 0.f;

    if (f0 < nf) {
        for (int i = d; i < Oo * FL * Hh; i += 1024) {
            int o = i >> 9, r = i & 511;   // r = fl*16 + h
            as[i] = attn[(size_t)o * (Ff * Bz * Hh) +
                         (size_t)(f0 + (r >> 4)) * (Bz * Hh) + b * Hh + (r & 15)];
        }
        __syncthreads();
        int fe = min(FL, nf - f0);
        const float* xp = x + ((size_t)f0 * Bz + b) * Dd + d;
        if (fe == FL) {
#pragma unroll 8
            for (int fl = 0; fl < FL; fl++) {
                float xv = xp[(size_t)fl * (Bz * Dd)];
                int ai = fl * 16 + h;
                a0 = fmaf(xv, as[ai],       a0);
                a1 = fmaf(xv, as[512 + ai], a1);
                a2 = fmaf(xv, as[1024 + ai], a2);
                a3 = fmaf(xv, as[1536 + ai], a3);
            }
        } else {
            for (int fl = 0; fl < fe; fl++) {
                float xv = xp[(size_t)fl * (Bz * Dd)];
                int ai = fl * 16 + h;
                a0 = fmaf(xv, as[ai],       a0);
                a1 = fmaf(xv, as[512 + ai], a1);
                a2 = fmaf(xv, as[1024 + ai], a2);
                a3 = fmaf(xv, as[1536 + ai], a3);
            }
        }
    }
    float* p = g_hcat_part + ((size_t)c * Bz + b) * FC + d;
    p[0] = a0; p[1024] = a1; p[2048] = a2; p[3072] = a3;
}

// Reduce the 16 chunk partials into hcat[b][o*1024+d]  (float4-wide, BW-bound)
__global__ void k_csum() {
    int i = (blockIdx.x * blockDim.x + threadIdx.x) * 4;
    float4 s = make_float4(0.f, 0.f, 0.f, 0.f);
#pragma unroll
    for (int c = 0; c < CH; c++) {
        float4 v = *(const float4*)&g_hcat_part[(size_t)c * (Bz * FC) + i];
        s.x += v.x; s.y += v.y; s.z += v.z; s.w += v.w;
    }
    *(float4*)&g_hcat[i] = s;
}

// ---------------------------------------------------------------------------
// Kernel D: hidden_part[kb][b][j] = sum_{k in 128-range} hcat[b][k] * W1[k][j]
// 1024 blocks (32 j x 32 k), 128 threads, acc[32], clean staging (32 LDG/thr).
// launch_bounds(128,6): 24 warps/SM resident, 1.15 waves — R8 showed the
// 512-block grid capped warps/SM at 13.8 regardless of bounds.
// ---------------------------------------------------------------------------
__global__ void __launch_bounds__(128, 6) k_gemm1(const float* __restrict__ W1) {
    int t = threadIdx.x;                  // 128
    int j = blockIdx.x * 128 + t;
    int kb = blockIdx.y * 128;

    __shared__ float hs[128 * 36];        // 18 KB, rows 16B-aligned
    float acc[32];
#pragma unroll
    for (int i = 0; i < 32; i++) acc[i] = 0.f;

    // Stage hcat tile transposed: thread t loads column (kb+t) over all 32 b.
#pragma unroll
    for (int b = 0; b < 32; b++)
        hs[t * 36 + b] = g_hcat[(size_t)b * FC + kb + t];
    __syncthreads();

    const float* wp = W1 + (size_t)kb * FC + j;
#pragma unroll 8
    for (int kl = 0; kl < 128; kl++) {
        float w = wp[(size_t)kl * FC];
        const float4* hp = (const float4*)&hs[kl * 36];
#pragma unroll
        for (int q4 = 0; q4 < 8; q4++) {
            float4 hv = hp[q4];
            acc[q4 * 4 + 0] = fmaf(hv.x, w, acc[q4 * 4 + 0]);
            acc[q4 * 4 + 1] = fmaf(hv.y, w, acc[q4 * 4 + 1]);
            acc[q4 * 4 + 2] = fmaf(hv.z, w, acc[q4 * 4 + 2]);
            acc[q4 * 4 + 3] = fmaf(hv.w, w, acc[q4 * 4 + 3]);
        }
    }

    float* dst = g_hidden_part + (size_t)blockIdx.y * (Bz * FC) + j;
#pragma unroll
    for (int b = 0; b < 32; b++) dst[(size_t)b * FC] = acc[b];
}

// ---------------------------------------------------------------------------
// Kernel E: out[b][n] = b2[n] + sum_j relu(sum_kb hidden_part + b1[j]) * W2[j][n]
// ---------------------------------------------------------------------------
__global__ void k_out(const float* __restrict__ b1, const float* __restrict__ W2,
                      const float* __restrict__ b2, float* __restrict__ out) {
    int b = blockIdx.x;
    int t = threadIdx.x;   // 256
    float a0 = 0.f, a1 = 0.f, a2 = 0.f, a3 = 0.f;

#pragma unroll
    for (int p = 0; p < 4; p++) {
        int j = (t + p * 256) * 4;
        float4 hv = *(const float4*)(b1 + j);
#pragma unroll
        for (int kb = 0; kb < NK; kb++) {
            float4 v = *(const float4*)&g_hidden_part[((size_t)kb * Bz + b) * FC + j];
            hv.x += v.x; hv.y += v.y; hv.z += v.z; hv.w += v.w;
        }
        hv.x = fmaxf(hv.x, 0.f); hv.y = fmaxf(hv.y, 0.f);
        hv.z = fmaxf(hv.z, 0.f); hv.w = fmaxf(hv.w, 0.f);
#pragma unroll
        for (int e = 0; e < 4; e++) {
            float h = e == 0 ? hv.x : e == 1 ? hv.y : e == 2 ? hv.z : hv.w;
            float4 w = *(const float4*)(W2 + (size_t)(j + e) * 4);
            a0 = fmaf(h, w.x, a0);
            a1 = fmaf(h, w.y, a1);
            a2 = fmaf(h, w.z, a2);
            a3 = fmaf(h, w.w, a3);
        }
    }
#pragma unroll
    for (int off = 16; off; off >>= 1) {
        a0 += __shfl_xor_sync(0xffffffffu, a0, off);
        a1 += __shfl_xor_sync(0xffffffffu, a1, off);
        a2 += __shfl_xor_sync(0xffffffffu, a2, off);
        a3 += __shfl_xor_sync(0xffffffffu, a3, off);
    }
    __shared__ float s[8][4];
    if ((t & 31) == 0) {
        int w = t >> 5;
        s[w][0] = a0; s[w][1] = a1; s[w][2] = a2; s[w][3] = a3;
    }
    __syncthreads();
    if (t < 4) {
        float r = 0.f;
#pragma unroll
        for (int w = 0; w < 8; w++) r += s[w][t];
        out[b * 4 + t] = r + b2[t];
    }
}

// ---------------------------------------------------------------------------
extern "C" void kernel_launch(void* const* d_in, const int* in_sizes, int n_in,
                              void* d_out, int out_size) {
    const float* x  = (const float*)d_in[0];
    const int*   nf = (const int*)  d_in[1];
    const float* q  = (const float*)d_in[2];
    const float* W1 = (const float*)d_in[3];
    const float* b1 = (const float*)d_in[4];
    const float* W2 = (const float*)d_in[5];
    const float* b2 = (const float*)d_in[6];

    float* out_p  = (float*)d_out;              // (B, 4) = 128 floats
    float* attn_p = out_p + Bz * Oo;            // (O, F, B, H) = 1,048,576 floats

    const int smemA = (64 * 67 + 8 * 1056) * 4; // 50944 B > 48 KB default
    cudaFuncSetAttribute(k_logits, cudaFuncAttributeMaxDynamicSharedMemorySize, smemA);

    dim3 gA(Bz, Ff / 8);
    k_logits<<<gA, 512, smemA>>>(x, nf, q);

    k_softmax<<<Oo * Bz, 256>>>(attn_p);

    dim3 gC(Bz, CH);
    k_wsum<<<gC, 1024>>>(x, nf, attn_p);

    k_csum<<<(Bz * FC) / (256 * 4), 256>>>();

    dim3 gD(FC / 128, NK);
    k_gemm1<<<gD, 128>>>(W1);

    k_out<<<Bz, 256>>>(b1, W2, b2, out_p);
}

// round 10
// speedup vs baseline: 1.1656x; 1.0757x over previous
#include <cuda_runtime.h>
#include <cstdint>
#include <cstddef>

#define Bz 32
#define Dd 1024
#define Ff 512
#define Hh 16
#define Oo 4
#define FC 4096
#define CH 16           // wsum chunks
#define FL 32           // frames per chunk
#define NK 32           // gemm1 k-splits

// Deterministic scratch (no device allocation allowed)
__device__ float g_logits[Oo * Bz * Hh * Ff];        // [o][b][h][f]  4 MB
__device__ float g_hcat_part[CH * Bz * FC];          // [chunk][b][o*1024+d] 8 MB
__device__ float g_hcat[Bz * FC];                    // [b][o*1024+d]  512 KB
__device__ float g_hidden_part[NK * Bz * FC];        // [kblk][b][j]  16 MB
__device__ float g_hidden[Bz * FC];                  // [b][j] post-ReLU
__device__ float g_dummy;

// Observability shim: shifts ncu's 4th-launch capture slot onto k_wsum.
__global__ void k_dummy() { g_dummy = 1.0f; }

// ---------------------------------------------------------------------------
// Kernel A: logits[o,b,h,f] = (x[f,b,h,:] . q[o,h,:]) / 8, masked to -50
// ---------------------------------------------------------------------------
__global__ void k_logits(const float* __restrict__ x, const int* __restrict__ nfp,
                         const float* __restrict__ q) {
    extern __shared__ float sm[];
    float* qs = sm;                 // 64 * 67
    float* xs = sm + 64 * 67;       // 8 * (16*66) = 8 * 1056
    int b  = blockIdx.x;
    int f0 = blockIdx.y * 8;
    int t  = threadIdx.x;
    int nf = nfp[b];

    for (int i = t; i < 64 * 64; i += 512)
        qs[(i >> 6) * 67 + (i & 63)] = q[i];

    for (int i = t; i < 8 * 512; i += 512) {
        int ff = i >> 9, j2 = i & 511;
        if (f0 + ff < nf) {
            int j = j2 * 2;
            float2 v = *(const float2*)&x[((size_t)(f0 + ff) * Bz + b) * Dd + j];
            *(float2*)&xs[ff * 1056 + (j >> 6) * 66 + (j & 63)] = v;
        }
    }
    __syncthreads();

    int fl = t >> 6;
    int oh = t & 63;
    int o = oh >> 4, h = oh & 15;
    int f = f0 + fl;

    float acc;
    if (f >= nf) {
        acc = -50.0f;
    } else {
        const float* xp = xs + fl * 1056 + h * 66;
        const float* qp = qs + oh * 67;
        float a = 0.f;
#pragma unroll
        for (int s = 0; s < 64; s++) a = fmaf(xp[s], qp[s], a);
        acc = a * 0.125f;
    }
    g_logits[((size_t)(o * Bz + b) * Hh + h) * Ff + f] = acc;
}

// ---------------------------------------------------------------------------
// Kernel B: softmax over f, writes attn in reference layout [o][f][b][h].
// ---------------------------------------------------------------------------
__global__ void k_softmax(float* __restrict__ attn) {
    int ob = blockIdx.x;
    int o = ob >> 5, b = ob & 31;
    int t = threadIdx.x;           // 256
    int w = t >> 5, lane = t & 31;

    __shared__ float ls[Hh * Ff];  // 32 KB
    __shared__ float si[Hh];

    const float* src = g_logits + (size_t)(o * Bz + b) * Hh * Ff;
    for (int i = t; i < Hh * Ff; i += 256) ls[i] = src[i];
    __syncthreads();

    for (int hh = w; hh < Hh; hh += 8) {
        float* lp = ls + hh * Ff;
        float m = -1e30f;
        for (int k = lane; k < Ff; k += 32) m = fmaxf(m, lp[k]);
#pragma unroll
        for (int off = 16; off; off >>= 1)
            m = fmaxf(m, __shfl_xor_sync(0xffffffffu, m, off));
        float s = 0.f;
        for (int k = lane; k < Ff; k += 32) {
            float e = __expf(lp[k] - m);
            lp[k] = e;
            s += e;
        }
#pragma unroll
        for (int off = 16; off; off >>= 1)
            s += __shfl_xor_sync(0xffffffffu, s, off);
        if (lane == 0) si[hh] = 1.0f / s;
    }
    __syncthreads();

    float* dst = attn + (size_t)o * Ff * Bz * Hh + b * Hh;
    for (int i = t; i < Hh * Ff; i += 256) {
        int f = i >> 4, hh = i & 15;
        dst[(size_t)f * (Bz * Hh) + hh] = ls[hh * Ff + f] * si[hh];
    }
}

// ---------------------------------------------------------------------------
// Kernel C: partial weighted sums, 16 chunks x 32 frames (MLP 8 via unroll).
// ---------------------------------------------------------------------------
__global__ void k_wsum(const float* __restrict__ x, const int* __restrict__ nfp,
                       const float* __restrict__ attn) {
    int b = blockIdx.x;
    int c = blockIdx.y;
    int f0 = c * FL;
    int nf = nfp[b];
    int d = threadIdx.x;
    int h = d >> 6;

    __shared__ float as[Oo * FL * Hh];   // [o][fl][h] 8 KB
    float a0 = 0.f, a1 = 0.f, a2 = 0.f, a3 = 0.f;

    if (f0 < nf) {
        for (int i = d; i < Oo * FL * Hh; i += 1024) {
            int o = i >> 9, r = i & 511;   // r = fl*16 + h
            as[i] = attn[(size_t)o * (Ff * Bz * Hh) +
                         (size_t)(f0 + (r >> 4)) * (Bz * Hh) + b * Hh + (r & 15)];
        }
        __syncthreads();
        int fe = min(FL, nf - f0);
        const float* xp = x + ((size_t)f0 * Bz + b) * Dd + d;
        if (fe == FL) {
#pragma unroll 8
            for (int fl = 0; fl < FL; fl++) {
                float xv = xp[(size_t)fl * (Bz * Dd)];
                int ai = fl * 16 + h;
                a0 = fmaf(xv, as[ai],       a0);
                a1 = fmaf(xv, as[512 + ai], a1);
                a2 = fmaf(xv, as[1024 + ai], a2);
                a3 = fmaf(xv, as[1536 + ai], a3);
            }
        } else {
            for (int fl = 0; fl < fe; fl++) {
                float xv = xp[(size_t)fl * (Bz * Dd)];
                int ai = fl * 16 + h;
                a0 = fmaf(xv, as[ai],       a0);
                a1 = fmaf(xv, as[512 + ai], a1);
                a2 = fmaf(xv, as[1024 + ai], a2);
                a3 = fmaf(xv, as[1536 + ai], a3);
            }
        }
    }
    float* p = g_hcat_part + ((size_t)c * Bz + b) * FC + d;
    p[0] = a0; p[1024] = a1; p[2048] = a2; p[3072] = a3;
}

// Reduce 16 chunk partials into hcat. Scalar, 131072 threads (512 blocks) —
// the R9 float4 version ran 128 blocks (<1/SM), occ 12%, issue 3.4%.
__global__ void k_csum() {
    int i = blockIdx.x * 256 + threadIdx.x;
    float s = 0.f;
#pragma unroll
    for (int c = 0; c < CH; c++) s += g_hcat_part[(size_t)c * (Bz * FC) + i];
    g_hcat[i] = s;
}

// ---------------------------------------------------------------------------
// Kernel D: hidden_part[kb][b][j] = sum_{k in 128-range} hcat[b][k] * W1[k][j]
// 1024 blocks (32 j x 32 k), 128 threads, acc[32], clean staging.
// ---------------------------------------------------------------------------
__global__ void __launch_bounds__(128, 6) k_gemm1(const float* __restrict__ W1) {
    int t = threadIdx.x;                  // 128
    int j = blockIdx.x * 128 + t;
    int kb = blockIdx.y * 128;

    __shared__ float hs[128 * 36];        // 18 KB, rows 16B-aligned
    float acc[32];
#pragma unroll
    for (int i = 0; i < 32; i++) acc[i] = 0.f;

#pragma unroll
    for (int b = 0; b < 32; b++)
        hs[t * 36 + b] = g_hcat[(size_t)b * FC + kb + t];
    __syncthreads();

    const float* wp = W1 + (size_t)kb * FC + j;
#pragma unroll 8
    for (int kl = 0; kl < 128; kl++) {
        float w = wp[(size_t)kl * FC];
        const float4* hp = (const float4*)&hs[kl * 36];
#pragma unroll
        for (int q4 = 0; q4 < 8; q4++) {
            float4 hv = hp[q4];
            acc[q4 * 4 + 0] = fmaf(hv.x, w, acc[q4 * 4 + 0]);
            acc[q4 * 4 + 1] = fmaf(hv.y, w, acc[q4 * 4 + 1]);
            acc[q4 * 4 + 2] = fmaf(hv.z, w, acc[q4 * 4 + 2]);
            acc[q4 * 4 + 3] = fmaf(hv.w, w, acc[q4 * 4 + 3]);
        }
    }

    float* dst = g_hidden_part + (size_t)blockIdx.y * (Bz * FC) + j;
#pragma unroll
    for (int b = 0; b < 32; b++) dst[(size_t)b * FC] = acc[b];
}

// Reduce 32 k-slabs + bias + ReLU into g_hidden. 512 blocks, full chip.
__global__ void k_hsum(const float* __restrict__ b1) {
    int i = blockIdx.x * 256 + threadIdx.x;   // over Bz*FC
    float s = b1[i & (FC - 1)];
#pragma unroll
    for (int kb = 0; kb < NK; kb++) s += g_hidden_part[(size_t)kb * (Bz * FC) + i];
    g_hidden[i] = fmaxf(s, 0.f);
}

// ---------------------------------------------------------------------------
// Kernel E: out[b][n] = b2[n] + sum_j hidden[b][j] * W2[j][n]  (hidden 512 KB)
// ---------------------------------------------------------------------------
__global__ void k_out(const float* __restrict__ W2, const float* __restrict__ b2,
                      float* __restrict__ out) {
    int b = blockIdx.x;
    int t = threadIdx.x;   // 256
    float a0 = 0.f, a1 = 0.f, a2 = 0.f, a3 = 0.f;

#pragma unroll
    for (int p = 0; p < 4; p++) {
        int j = (t + p * 256) * 4;
        float4 hv = *(const float4*)&g_hidden[(size_t)b * FC + j];
#pragma unroll
        for (int e = 0; e < 4; e++) {
            float h = e == 0 ? hv.x : e == 1 ? hv.y : e == 2 ? hv.z : hv.w;
            float4 w = *(const float4*)(W2 + (size_t)(j + e) * 4);
            a0 = fmaf(h, w.x, a0);
            a1 = fmaf(h, w.y, a1);
            a2 = fmaf(h, w.z, a2);
            a3 = fmaf(h, w.w, a3);
        }
    }
#pragma unroll
    for (int off = 16; off; off >>= 1) {
        a0 += __shfl_xor_sync(0xffffffffu, a0, off);
        a1 += __shfl_xor_sync(0xffffffffu, a1, off);
        a2 += __shfl_xor_sync(0xffffffffu, a2, off);
        a3 += __shfl_xor_sync(0xffffffffu, a3, off);
    }
    __shared__ float s[8][4];
    if ((t & 31) == 0) {
        int w = t >> 5;
        s[w][0] = a0; s[w][1] = a1; s[w][2] = a2; s[w][3] = a3;
    }
    __syncthreads();
    if (t < 4) {
        float r = 0.f;
#pragma unroll
        for (int w = 0; w < 8; w++) r += s[w][t];
        out[b * 4 + t] = r + b2[t];
    }
}

// ---------------------------------------------------------------------------
extern "C" void kernel_launch(void* const* d_in, const int* in_sizes, int n_in,
                              void* d_out, int out_size) {
    const float* x  = (const float*)d_in[0];
    const int*   nf = (const int*)  d_in[1];
    const float* q  = (const float*)d_in[2];
    const float* W1 = (const float*)d_in[3];
    const float* b1 = (const float*)d_in[4];
    const float* W2 = (const float*)d_in[5];
    const float* b2 = (const float*)d_in[6];

    float* out_p  = (float*)d_out;              // (B, 4) = 128 floats
    float* attn_p = out_p + Bz * Oo;            // (O, F, B, H) = 1,048,576 floats

    const int smemA = (64 * 67 + 8 * 1056) * 4; // 50944 B > 48 KB default
    cudaFuncSetAttribute(k_logits, cudaFuncAttributeMaxDynamicSharedMemorySize, smemA);

    k_dummy<<<1, 1>>>();                        // capture slot -> k_wsum

    dim3 gA(Bz, Ff / 8);
    k_logits<<<gA, 512, smemA>>>(x, nf, q);

    k_softmax<<<Oo * Bz, 256>>>(attn_p);

    dim3 gC(Bz, CH);
    k_wsum<<<gC, 1024>>>(x, nf, attn_p);        // 4th launch (ncu)

    k_csum<<<(Bz * FC) / 256, 256>>>();

    dim3 gD(FC / 128, NK);
    k_gemm1<<<gD, 128>>>(W1);

    k_hsum<<<(Bz * FC) / 256, 256>>>(b1);

    k_out<<<Bz, 256>>>(W2, b2, out_p);
}

// round 11
// speedup vs baseline: 1.2342x; 1.0589x over previous
#include <cuda_runtime.h>
#include <cstdint>
#include <cstddef>

#define Bz 32
#define Dd 1024
#define Ff 512
#define Hh 16
#define Oo 4
#define FC 4096
#define CH 16           // wsum chunks
#define FL 32           // frames per chunk
#define NK 16           // gemm k-splits (k-chunk 256)

// Deterministic scratch (no device allocation allowed)
__device__ float g_logits[Oo * Bz * Hh * Ff];        // [o][b][h][f]  4 MB
__device__ float g_hcat_part[CH * Bz * FC];          // [chunk][b][o*1024+d] 8 MB
__device__ float g_hcat[Bz * FC];                    // [b][o*1024+d]  512 KB
__device__ float g_hidden_part[NK * Bz * FC];        // [kblk][b][j]  8 MB
__device__ float g_hidden[Bz * FC];                  // [b][j] post-ReLU

// ---------------------------------------------------------------------------
// Kernel A: logits[o,b,h,f] = (x[f,b,h,:] . q[o,h,:]) / 8, masked to -50
// ---------------------------------------------------------------------------
__global__ void k_logits(const float* __restrict__ x, const int* __restrict__ nfp,
                         const float* __restrict__ q) {
    extern __shared__ float sm[];
    float* qs = sm;                 // 64 * 67
    float* xs = sm + 64 * 67;       // 8 * (16*66) = 8 * 1056
    int b  = blockIdx.x;
    int f0 = blockIdx.y * 8;
    int t  = threadIdx.x;
    int nf = nfp[b];

    for (int i = t; i < 64 * 64; i += 512)
        qs[(i >> 6) * 67 + (i & 63)] = q[i];

    for (int i = t; i < 8 * 512; i += 512) {
        int ff = i >> 9, j2 = i & 511;
        if (f0 + ff < nf) {
            int j = j2 * 2;
            float2 v = *(const float2*)&x[((size_t)(f0 + ff) * Bz + b) * Dd + j];
            *(float2*)&xs[ff * 1056 + (j >> 6) * 66 + (j & 63)] = v;
        }
    }
    __syncthreads();

    int fl = t >> 6;
    int oh = t & 63;
    int o = oh >> 4, h = oh & 15;
    int f = f0 + fl;

    float acc;
    if (f >= nf) {
        acc = -50.0f;
    } else {
        const float* xp = xs + fl * 1056 + h * 66;
        const float* qp = qs + oh * 67;
        float a = 0.f;
#pragma unroll
        for (int s = 0; s < 64; s++) a = fmaf(xp[s], qp[s], a);
        acc = a * 0.125f;
    }
    g_logits[((size_t)(o * Bz + b) * Hh + h) * Ff + f] = acc;
}

// ---------------------------------------------------------------------------
// Kernel B: softmax over f, writes attn in reference layout [o][f][b][h].
// ---------------------------------------------------------------------------
__global__ void k_softmax(float* __restrict__ attn) {
    int ob = blockIdx.x;
    int o = ob >> 5, b = ob & 31;
    int t = threadIdx.x;           // 256
    int w = t >> 5, lane = t & 31;

    __shared__ float ls[Hh * Ff];  // 32 KB
    __shared__ float si[Hh];

    const float* src = g_logits + (size_t)(o * Bz + b) * Hh * Ff;
    for (int i = t; i < Hh * Ff; i += 256) ls[i] = src[i];
    __syncthreads();

    for (int hh = w; hh < Hh; hh += 8) {
        float* lp = ls + hh * Ff;
        float m = -1e30f;
        for (int k = lane; k < Ff; k += 32) m = fmaxf(m, lp[k]);
#pragma unroll
        for (int off = 16; off; off >>= 1)
            m = fmaxf(m, __shfl_xor_sync(0xffffffffu, m, off));
        float s = 0.f;
        for (int k = lane; k < Ff; k += 32) {
            float e = __expf(lp[k] - m);
            lp[k] = e;
            s += e;
        }
#pragma unroll
        for (int off = 16; off; off >>= 1)
            s += __shfl_xor_sync(0xffffffffu, s, off);
        if (lane == 0) si[hh] = 1.0f / s;
    }
    __syncthreads();

    float* dst = attn + (size_t)o * Ff * Bz * Hh + b * Hh;
    for (int i = t; i < Hh * Ff; i += 256) {
        int f = i >> 4, hh = i & 15;
        dst[(size_t)f * (Bz * Hh) + hh] = ls[hh * Ff + f] * si[hh];
    }
}

// ---------------------------------------------------------------------------
// Kernel C: partial weighted sums, 16 chunks x 32 frames (MLP 8 via unroll).
// ---------------------------------------------------------------------------
__global__ void k_wsum(const float* __restrict__ x, const int* __restrict__ nfp,
                       const float* __restrict__ attn) {
    int b = blockIdx.x;
    int c = blockIdx.y;
    int f0 = c * FL;
    int nf = nfp[b];
    int d = threadIdx.x;
    int h = d >> 6;

    __shared__ float as[Oo * FL * Hh];   // [o][fl][h] 8 KB
    float a0 = 0.f, a1 = 0.f, a2 = 0.f, a3 = 0.f;

    if (f0 < nf) {
        for (int i = d; i < Oo * FL * Hh; i += 1024) {
            int o = i >> 9, r = i & 511;   // r = fl*16 + h
            as[i] = attn[(size_t)o * (Ff * Bz * Hh) +
                         (size_t)(f0 + (r >> 4)) * (Bz * Hh) + b * Hh + (r & 15)];
        }
        __syncthreads();
        int fe = min(FL, nf - f0);
        const float* xp = x + ((size_t)f0 * Bz + b) * Dd + d;
        if (fe == FL) {
#pragma unroll 8
            for (int fl = 0; fl < FL; fl++) {
                float xv = xp[(size_t)fl * (Bz * Dd)];
                int ai = fl * 16 + h;
                a0 = fmaf(xv, as[ai],       a0);
                a1 = fmaf(xv, as[512 + ai], a1);
                a2 = fmaf(xv, as[1024 + ai], a2);
                a3 = fmaf(xv, as[1536 + ai], a3);
            }
        } else {
            for (int fl = 0; fl < fe; fl++) {
                float xv = xp[(size_t)fl * (Bz * Dd)];
                int ai = fl * 16 + h;
                a0 = fmaf(xv, as[ai],       a0);
                a1 = fmaf(xv, as[512 + ai], a1);
                a2 = fmaf(xv, as[1024 + ai], a2);
                a3 = fmaf(xv, as[1536 + ai], a3);
            }
        }
    }
    float* p = g_hcat_part + ((size_t)c * Bz + b) * FC + d;
    p[0] = a0; p[1024] = a1; p[2048] = a2; p[3072] = a3;
}

// Reduce 16 chunk partials into hcat. Scalar, 512 blocks, full-chip.
__global__ void k_csum() {
    int i = blockIdx.x * 256 + threadIdx.x;
    float s = 0.f;
#pragma unroll
    for (int c = 0; c < CH; c++) s += g_hcat_part[(size_t)c * (Bz * FC) + i];
    g_hcat[i] = s;
}

// ---------------------------------------------------------------------------
// Kernel D: 3xTF32 tensor-core GEMM.
// hidden_part[kb][b][j] = sum_{k in 256-chunk} hcat[b][k] * W1[k][j]
// Block: 256 thr (8 warps), j-tile 128 (16 cols/warp), k-chunk 256.
// Grid 32 x 16 = 512 blocks. A (hcat) staged hi/lo tf32 in smem once/block;
// W1 staged 8x128 per k-step; mma m16n8k8, D = hi*hi + lo*hi + hi*lo.
// ---------------------------------------------------------------------------
#define AP 260          // A smem row pitch (bank (4g+t)%32 conflict-free)
#define WP 136          // W smem row pitch (bank (8t+g)%32 conflict-free)

__device__ __forceinline__ uint32_t f2tf32(float x) {
    uint32_t r;
    asm("cvt.rna.tf32.f32 %0, %1;" : "=r"(r) : "f"(x));
    return r;
}

__device__ __forceinline__ void mma_tf32(float* d, const uint32_t* a,
                                         uint32_t b0, uint32_t b1) {
    asm("mma.sync.aligned.m16n8k8.row.col.f32.tf32.tf32.f32 "
        "{%0,%1,%2,%3}, {%4,%5,%6,%7}, {%8,%9}, {%0,%1,%2,%3};"
        : "+f"(d[0]), "+f"(d[1]), "+f"(d[2]), "+f"(d[3])
        : "r"(a[0]), "r"(a[1]), "r"(a[2]), "r"(a[3]), "r"(b0), "r"(b1));
}

__global__ void __launch_bounds__(256, 3) k_gemm1(const float* __restrict__ W1) {
    extern __shared__ float smg[];
    float* Ah = smg;                 // 32 * AP
    float* Al = Ah + 32 * AP;        // 32 * AP
    float* Ws = Al + 32 * AP;        // 8 * WP
    int t = threadIdx.x;
    int warp = t >> 5, lane = t & 31;
    int g = lane >> 2, tg = lane & 3;
    int jb = blockIdx.x * 128;
    int kb = blockIdx.y * 256;

    // Stage A = hcat[0..31][kb..kb+255] as hi/lo tf32
    for (int idx = t; idx < 32 * 256; idx += 256) {
        int b = idx >> 8, c = idx & 255;
        float v = g_hcat[b * FC + kb + c];
        uint32_t hi = f2tf32(v);
        float lof = v - __uint_as_float(hi);
        Ah[b * AP + c] = __uint_as_float(hi);
        Al[b * AP + c] = __uint_as_float(f2tf32(lof));
    }

    float d[2][2][4];
#pragma unroll
    for (int mt = 0; mt < 2; mt++)
#pragma unroll
        for (int nt = 0; nt < 2; nt++)
#pragma unroll
            for (int e = 0; e < 4; e++) d[mt][nt][e] = 0.f;

    int wr = t >> 5;           // 0..7: W row within 8-row stage
    int wc = t & 31;           // 0..31: float4 column
    for (int ks = 0; ks < 32; ks++) {
        __syncthreads();
        float4 wv = *(const float4*)&W1[(size_t)(kb + ks * 8 + wr) * FC + jb + wc * 4];
        *(float4*)&Ws[wr * WP + wc * 4] = wv;
        __syncthreads();

        // A fragments (shared across nt)
        int ac = ks * 8 + tg;
        uint32_t ah[2][4], al[2][4];
#pragma unroll
        for (int mt = 0; mt < 2; mt++) {
            int r0 = mt * 16 + g;
            ah[mt][0] = __float_as_uint(Ah[r0 * AP + ac]);
            ah[mt][1] = __float_as_uint(Ah[(r0 + 8) * AP + ac]);
            ah[mt][2] = __float_as_uint(Ah[r0 * AP + ac + 4]);
            ah[mt][3] = __float_as_uint(Ah[(r0 + 8) * AP + ac + 4]);
            al[mt][0] = __float_as_uint(Al[r0 * AP + ac]);
            al[mt][1] = __float_as_uint(Al[(r0 + 8) * AP + ac]);
            al[mt][2] = __float_as_uint(Al[r0 * AP + ac + 4]);
            al[mt][3] = __float_as_uint(Al[(r0 + 8) * AP + ac + 4]);
        }

#pragma unroll
        for (int nt = 0; nt < 2; nt++) {
            int jc = warp * 16 + nt * 8 + g;
            float b0f = Ws[tg * WP + jc];
            float b1f = Ws[(tg + 4) * WP + jc];
            uint32_t bh0 = f2tf32(b0f);
            uint32_t bl0 = f2tf32(b0f - __uint_as_float(bh0));
            uint32_t bh1 = f2tf32(b1f);
            uint32_t bl1 = f2tf32(b1f - __uint_as_float(bh1));
#pragma unroll
            for (int mt = 0; mt < 2; mt++) {
                mma_tf32(d[mt][nt], ah[mt], bh0, bh1);
                mma_tf32(d[mt][nt], al[mt], bh0, bh1);
                mma_tf32(d[mt][nt], ah[mt], bl0, bl1);
            }
        }
    }

    // Write D: row b = mt*16 + g (+8), col j = jb + warp*16 + nt*8 + 2*tg (+1)
    float* dst = g_hidden_part + (size_t)blockIdx.y * (Bz * FC);
#pragma unroll
    for (int mt = 0; mt < 2; mt++) {
#pragma unroll
        for (int nt = 0; nt < 2; nt++) {
            int j0 = jb + warp * 16 + nt * 8 + 2 * tg;
            int b0 = mt * 16 + g;
            *(float2*)&dst[(size_t)b0 * FC + j0] =
                make_float2(d[mt][nt][0], d[mt][nt][1]);
            *(float2*)&dst[(size_t)(b0 + 8) * FC + j0] =
                make_float2(d[mt][nt][2], d[mt][nt][3]);
        }
    }
}

// Reduce 16 k-slabs + bias + ReLU into g_hidden. 512 blocks, full chip.
__global__ void k_hsum(const float* __restrict__ b1) {
    int i = blockIdx.x * 256 + threadIdx.x;   // over Bz*FC
    float s = b1[i & (FC - 1)];
#pragma unroll
    for (int kb = 0; kb < NK; kb++) s += g_hidden_part[(size_t)kb * (Bz * FC) + i];
    g_hidden[i] = fmaxf(s, 0.f);
}

// ---------------------------------------------------------------------------
// Kernel E: out[b][n] = b2[n] + sum_j hidden[b][j] * W2[j][n]
// ---------------------------------------------------------------------------
__global__ void k_out(const float* __restrict__ W2, const float* __restrict__ b2,
                      float* __restrict__ out) {
    int b = blockIdx.x;
    int t = threadIdx.x;   // 256
    float a0 = 0.f, a1 = 0.f, a2 = 0.f, a3 = 0.f;

#pragma unroll
    for (int p = 0; p < 4; p++) {
        int j = (t + p * 256) * 4;
        float4 hv = *(const float4*)&g_hidden[(size_t)b * FC + j];
#pragma unroll
        for (int e = 0; e < 4; e++) {
            float h = e == 0 ? hv.x : e == 1 ? hv.y : e == 2 ? hv.z : hv.w;
            float4 w = *(const float4*)(W2 + (size_t)(j + e) * 4);
            a0 = fmaf(h, w.x, a0);
            a1 = fmaf(h, w.y, a1);
            a2 = fmaf(h, w.z, a2);
            a3 = fmaf(h, w.w, a3);
        }
    }
#pragma unroll
    for (int off = 16; off; off >>= 1) {
        a0 += __shfl_xor_sync(0xffffffffu, a0, off);
        a1 += __shfl_xor_sync(0xffffffffu, a1, off);
        a2 += __shfl_xor_sync(0xffffffffu, a2, off);
        a3 += __shfl_xor_sync(0xffffffffu, a3, off);
    }
    __shared__ float s[8][4];
    if ((t & 31) == 0) {
        int w = t >> 5;
        s[w][0] = a0; s[w][1] = a1; s[w][2] = a2; s[w][3] = a3;
    }
    __syncthreads();
    if (t < 4) {
        float r = 0.f;
#pragma unroll
        for (int w = 0; w < 8; w++) r += s[w][t];
        out[b * 4 + t] = r + b2[t];
    }
}

// ---------------------------------------------------------------------------
extern "C" void kernel_launch(void* const* d_in, const int* in_sizes, int n_in,
                              void* d_out, int out_size) {
    const float* x  = (const float*)d_in[0];
    const int*   nf = (const int*)  d_in[1];
    const float* q  = (const float*)d_in[2];
    const float* W1 = (const float*)d_in[3];
    const float* b1 = (const float*)d_in[4];
    const float* W2 = (const float*)d_in[5];
    const float* b2 = (const float*)d_in[6];

    float* out_p  = (float*)d_out;              // (B, 4) = 128 floats
    float* attn_p = out_p + Bz * Oo;            // (O, F, B, H) = 1,048,576 floats

    const int smemA = (64 * 67 + 8 * 1056) * 4; // 50944 B
    cudaFuncSetAttribute(k_logits, cudaFuncAttributeMaxDynamicSharedMemorySize, smemA);
    const int smemG = (2 * 32 * AP + 8 * WP) * 4;  // 70912 B
    cudaFuncSetAttribute(k_gemm1, cudaFuncAttributeMaxDynamicSharedMemorySize, smemG);

    dim3 gA(Bz, Ff / 8);
    k_logits<<<gA, 512, smemA>>>(x, nf, q);

    k_softmax<<<Oo * Bz, 256>>>(attn_p);

    dim3 gC(Bz, CH);
    k_wsum<<<gC, 1024>>>(x, nf, attn_p);

    k_csum<<<(Bz * FC) / 256, 256>>>();         // 4th launch (ncu)

    dim3 gD(FC / 128, NK);
    k_gemm1<<<gD, 256, smemG>>>(W1);

    k_hsum<<<(Bz * FC) / 256, 256>>>(b1);

    k_out<<<Bz, 256>>>(W2, b2, out_p);
}

// round 12
// speedup vs baseline: 1.3414x; 1.0868x over previous
#include <cuda_runtime.h>
#include <cstdint>
#include <cstddef>

#define Bz 32
#define Dd 1024
#define Ff 512
#define Hh 16
#define Oo 4
#define FC 4096
#define CH 16           // wsum chunks
#define FL 32           // frames per chunk
#define NK 16           // gemm k-splits (k-chunk 256)

// Deterministic scratch (no device allocation allowed)
__device__ float g_logits[Oo * Bz * Hh * Ff];        // [o][b][h][f]  4 MB
__device__ float g_hcat_part[CH * Bz * FC];          // [chunk][b][o*1024+d] 8 MB
__device__ float g_hcat[Bz * FC];                    // [b][o*1024+d]  512 KB
__device__ float g_hidden_part[NK * Bz * FC];        // [kblk][b][j]  8 MB
__device__ float g_hidden[Bz * FC];                  // [b][j] post-ReLU

// ---------------------------------------------------------------------------
// Kernel A: logits[o,b,h,f] = (x[f,b,h,:] . q[o,h,:]) / 8, masked to -50
// ---------------------------------------------------------------------------
__global__ void k_logits(const float* __restrict__ x, const int* __restrict__ nfp,
                         const float* __restrict__ q) {
    extern __shared__ float sm[];
    float* qs = sm;                 // 64 * 67
    float* xs = sm + 64 * 67;       // 8 * (16*66) = 8 * 1056
    int b  = blockIdx.x;
    int f0 = blockIdx.y * 8;
    int t  = threadIdx.x;
    int nf = nfp[b];

    for (int i = t; i < 64 * 64; i += 512)
        qs[(i >> 6) * 67 + (i & 63)] = q[i];

    for (int i = t; i < 8 * 512; i += 512) {
        int ff = i >> 9, j2 = i & 511;
        if (f0 + ff < nf) {
            int j = j2 * 2;
            float2 v = *(const float2*)&x[((size_t)(f0 + ff) * Bz + b) * Dd + j];
            *(float2*)&xs[ff * 1056 + (j >> 6) * 66 + (j & 63)] = v;
        }
    }
    __syncthreads();

    int fl = t >> 6;
    int oh = t & 63;
    int o = oh >> 4, h = oh & 15;
    int f = f0 + fl;

    float acc;
    if (f >= nf) {
        acc = -50.0f;
    } else {
        const float* xp = xs + fl * 1056 + h * 66;
        const float* qp = qs + oh * 67;
        float a = 0.f;
#pragma unroll
        for (int s = 0; s < 64; s++) a = fmaf(xp[s], qp[s], a);
        acc = a * 0.125f;
    }
    g_logits[((size_t)(o * Bz + b) * Hh + h) * Ff + f] = acc;
}

// ---------------------------------------------------------------------------
// Kernel B: softmax over f, writes attn in reference layout [o][f][b][h].
// ---------------------------------------------------------------------------
__global__ void k_softmax(float* __restrict__ attn) {
    int ob = blockIdx.x;
    int o = ob >> 5, b = ob & 31;
    int t = threadIdx.x;           // 256
    int w = t >> 5, lane = t & 31;

    __shared__ float ls[Hh * Ff];  // 32 KB
    __shared__ float si[Hh];

    const float* src = g_logits + (size_t)(o * Bz + b) * Hh * Ff;
    for (int i = t; i < Hh * Ff; i += 256) ls[i] = src[i];
    __syncthreads();

    for (int hh = w; hh < Hh; hh += 8) {
        float* lp = ls + hh * Ff;
        float m = -1e30f;
        for (int k = lane; k < Ff; k += 32) m = fmaxf(m, lp[k]);
#pragma unroll
        for (int off = 16; off; off >>= 1)
            m = fmaxf(m, __shfl_xor_sync(0xffffffffu, m, off));
        float s = 0.f;
        for (int k = lane; k < Ff; k += 32) {
            float e = __expf(lp[k] - m);
            lp[k] = e;
            s += e;
        }
#pragma unroll
        for (int off = 16; off; off >>= 1)
            s += __shfl_xor_sync(0xffffffffu, s, off);
        if (lane == 0) si[hh] = 1.0f / s;
    }
    __syncthreads();

    float* dst = attn + (size_t)o * Ff * Bz * Hh + b * Hh;
    for (int i = t; i < Hh * Ff; i += 256) {
        int f = i >> 4, hh = i & 15;
        dst[(size_t)f * (Bz * Hh) + hh] = ls[hh * Ff + f] * si[hh];
    }
}

// ---------------------------------------------------------------------------
// Kernel C: partial weighted sums, 16 chunks x 32 frames (unroll 16 -> MLP 16).
// ---------------------------------------------------------------------------
__global__ void k_wsum(const float* __restrict__ x, const int* __restrict__ nfp,
                       const float* __restrict__ attn) {
    int b = blockIdx.x;
    int c = blockIdx.y;
    int f0 = c * FL;
    int nf = nfp[b];
    int d = threadIdx.x;
    int h = d >> 6;

    __shared__ float as[Oo * FL * Hh];   // [o][fl][h] 8 KB
    float a0 = 0.f, a1 = 0.f, a2 = 0.f, a3 = 0.f;

    if (f0 < nf) {
        for (int i = d; i < Oo * FL * Hh; i += 1024) {
            int o = i >> 9, r = i & 511;   // r = fl*16 + h
            as[i] = attn[(size_t)o * (Ff * Bz * Hh) +
                         (size_t)(f0 + (r >> 4)) * (Bz * Hh) + b * Hh + (r & 15)];
        }
        __syncthreads();
        int fe = min(FL, nf - f0);
        const float* xp = x + ((size_t)f0 * Bz + b) * Dd + d;
        if (fe == FL) {
#pragma unroll 16
            for (int fl = 0; fl < FL; fl++) {
                float xv = xp[(size_t)fl * (Bz * Dd)];
                int ai = fl * 16 + h;
                a0 = fmaf(xv, as[ai],       a0);
                a1 = fmaf(xv, as[512 + ai], a1);
                a2 = fmaf(xv, as[1024 + ai], a2);
                a3 = fmaf(xv, as[1536 + ai], a3);
            }
        } else {
            for (int fl = 0; fl < fe; fl++) {
                float xv = xp[(size_t)fl * (Bz * Dd)];
                int ai = fl * 16 + h;
                a0 = fmaf(xv, as[ai],       a0);
                a1 = fmaf(xv, as[512 + ai], a1);
                a2 = fmaf(xv, as[1024 + ai], a2);
                a3 = fmaf(xv, as[1536 + ai], a3);
            }
        }
    }
    float* p = g_hcat_part + ((size_t)c * Bz + b) * FC + d;
    p[0] = a0; p[1024] = a1; p[2048] = a2; p[3072] = a3;
}

// Reduce 16 chunk partials into hcat. Scalar, 512 blocks, full-chip.
__global__ void k_csum() {
    int i = blockIdx.x * 256 + threadIdx.x;
    float s = 0.f;
#pragma unroll
    for (int c = 0; c < CH; c++) s += g_hcat_part[(size_t)c * (Bz * FC) + i];
    g_hcat[i] = s;
}

// ---------------------------------------------------------------------------
// Kernel D: 3xTF32 tensor-core GEMM, double-buffered W1 pipeline.
// hidden_part[kb][b][j] = sum_{k in 256-chunk} hcat[b][k] * W1[k][j]
// 16 iterations of k=16; per iter: prefetch next W stage (2 LDG.128/thread)
// BEFORE compute, store after, one barrier. LDG latency hides under 24 mma.
// ---------------------------------------------------------------------------
#define AP 260          // A smem row pitch (bank (4g+tg)%32 conflict-free)
#define WP 136          // W smem row pitch (bank (8tg+g)%32 conflict-free)

__device__ __forceinline__ uint32_t f2tf32(float x) {
    uint32_t r;
    asm("cvt.rna.tf32.f32 %0, %1;" : "=r"(r) : "f"(x));
    return r;
}

__device__ __forceinline__ void mma_tf32(float* d, const uint32_t* a,
                                         uint32_t b0, uint32_t b1) {
    asm("mma.sync.aligned.m16n8k8.row.col.f32.tf32.tf32.f32 "
        "{%0,%1,%2,%3}, {%4,%5,%6,%7}, {%8,%9}, {%0,%1,%2,%3};"
        : "+f"(d[0]), "+f"(d[1]), "+f"(d[2]), "+f"(d[3])
        : "r"(a[0]), "r"(a[1]), "r"(a[2]), "r"(a[3]), "r"(b0), "r"(b1));
}

__global__ void __launch_bounds__(256, 2) k_gemm1(const float* __restrict__ W1) {
    extern __shared__ float smg[];
    float* Ah = smg;                 // 32 * AP
    float* Al = Ah + 32 * AP;        // 32 * AP
    float* Ws = Al + 32 * AP;        // 2 * 16 * WP (double buffer)
    int t = threadIdx.x;
    int warp = t >> 5, lane = t & 31;
    int g = lane >> 2, tg = lane & 3;
    int jb = blockIdx.x * 128;
    int kb = blockIdx.y * 256;

    // Stage A = hcat[0..31][kb..kb+255] as hi/lo tf32
    for (int idx = t; idx < 32 * 256; idx += 256) {
        int b = idx >> 8, c = idx & 255;
        float v = g_hcat[b * FC + kb + c];
        uint32_t hi = f2tf32(v);
        float lof = v - __uint_as_float(hi);
        Ah[b * AP + c] = __uint_as_float(hi);
        Al[b * AP + c] = __uint_as_float(f2tf32(lof));
    }

    float d[2][2][4];
#pragma unroll
    for (int mt = 0; mt < 2; mt++)
#pragma unroll
        for (int nt = 0; nt < 2; nt++)
#pragma unroll
            for (int e = 0; e < 4; e++) d[mt][nt][e] = 0.f;

    // W stage: 16 rows x 128 cols. Thread t owns rows (t>>5) and (t>>5)+8,
    // float4 column (t&31)*4.
    int wrow = t >> 5;
    int wcol = (t & 31) * 4;
    const float* wbase = W1 + (size_t)kb * FC + jb + wcol;

    float4 p0 = *(const float4*)(wbase + (size_t)wrow * FC);
    float4 p1 = *(const float4*)(wbase + (size_t)(wrow + 8) * FC);
    __syncthreads();                       // A staging complete
    *(float4*)&Ws[wrow * WP + wcol] = p0;
    *(float4*)&Ws[(wrow + 8) * WP + wcol] = p1;
    __syncthreads();

    for (int ks = 0; ks < 16; ks++) {
        const float* Wcur = Ws + (ks & 1) * (16 * WP);
        float* Wnxt = Ws + ((ks & 1) ^ 1) * (16 * WP);
        if (ks < 15) {
            p0 = *(const float4*)(wbase + (size_t)((ks + 1) * 16 + wrow) * FC);
            p1 = *(const float4*)(wbase + (size_t)((ks + 1) * 16 + wrow + 8) * FC);
        }

#pragma unroll
        for (int sub = 0; sub < 2; sub++) {
            int ac = ks * 16 + sub * 8 + tg;
            uint32_t ah[2][4], al[2][4];
#pragma unroll
            for (int mt = 0; mt < 2; mt++) {
                int r0 = mt * 16 + g;
                ah[mt][0] = __float_as_uint(Ah[r0 * AP + ac]);
                ah[mt][1] = __float_as_uint(Ah[(r0 + 8) * AP + ac]);
                ah[mt][2] = __float_as_uint(Ah[r0 * AP + ac + 4]);
                ah[mt][3] = __float_as_uint(Ah[(r0 + 8) * AP + ac + 4]);
                al[mt][0] = __float_as_uint(Al[r0 * AP + ac]);
                al[mt][1] = __float_as_uint(Al[(r0 + 8) * AP + ac]);
                al[mt][2] = __float_as_uint(Al[r0 * AP + ac + 4]);
                al[mt][3] = __float_as_uint(Al[(r0 + 8) * AP + ac + 4]);
            }
#pragma unroll
            for (int nt = 0; nt < 2; nt++) {
                int jc = warp * 16 + nt * 8 + g;
                float b0f = Wcur[(sub * 8 + tg) * WP + jc];
                float b1f = Wcur[(sub * 8 + tg + 4) * WP + jc];
                uint32_t bh0 = f2tf32(b0f);
                uint32_t bl0 = f2tf32(b0f - __uint_as_float(bh0));
                uint32_t bh1 = f2tf32(b1f);
                uint32_t bl1 = f2tf32(b1f - __uint_as_float(bh1));
#pragma unroll
                for (int mt = 0; mt < 2; mt++) {
                    mma_tf32(d[mt][nt], ah[mt], bh0, bh1);
                    mma_tf32(d[mt][nt], al[mt], bh0, bh1);
                    mma_tf32(d[mt][nt], ah[mt], bl0, bl1);
                }
            }
        }

        if (ks < 15) {
            *(float4*)&Wnxt[wrow * WP + wcol] = p0;
            *(float4*)&Wnxt[(wrow + 8) * WP + wcol] = p1;
        }
        __syncthreads();
    }

    // Write D: row b = mt*16 + g (+8), col j = jb + warp*16 + nt*8 + 2*tg (+1)
    float* dst = g_hidden_part + (size_t)blockIdx.y * (Bz * FC);
#pragma unroll
    for (int mt = 0; mt < 2; mt++) {
#pragma unroll
        for (int nt = 0; nt < 2; nt++) {
            int j0 = jb + warp * 16 + nt * 8 + 2 * tg;
            int b0 = mt * 16 + g;
            *(float2*)&dst[(size_t)b0 * FC + j0] =
                make_float2(d[mt][nt][0], d[mt][nt][1]);
            *(float2*)&dst[(size_t)(b0 + 8) * FC + j0] =
                make_float2(d[mt][nt][2], d[mt][nt][3]);
        }
    }
}

// Reduce 16 k-slabs + bias + ReLU into g_hidden. 512 blocks, full chip.
__global__ void k_hsum(const float* __restrict__ b1) {
    int i = blockIdx.x * 256 + threadIdx.x;   // over Bz*FC
    float s = b1[i & (FC - 1)];
#pragma unroll
    for (int kb = 0; kb < NK; kb++) s += g_hidden_part[(size_t)kb * (Bz * FC) + i];
    g_hidden[i] = fmaxf(s, 0.f);
}

// ---------------------------------------------------------------------------
// Kernel E: out[b][n] = b2[n] + sum_j hidden[b][j] * W2[j][n]
// ---------------------------------------------------------------------------
__global__ void k_out(const float* __restrict__ W2, const float* __restrict__ b2,
                      float* __restrict__ out) {
    int b = blockIdx.x;
    int t = threadIdx.x;   // 256
    float a0 = 0.f, a1 = 0.f, a2 = 0.f, a3 = 0.f;

#pragma unroll
    for (int p = 0; p < 4; p++) {
        int j = (t + p * 256) * 4;
        float4 hv = *(const float4*)&g_hidden[(size_t)b * FC + j];
#pragma unroll
        for (int e = 0; e < 4; e++) {
            float h = e == 0 ? hv.x : e == 1 ? hv.y : e == 2 ? hv.z : hv.w;
            float4 w = *(const float4*)(W2 + (size_t)(j + e) * 4);
            a0 = fmaf(h, w.x, a0);
            a1 = fmaf(h, w.y, a1);
            a2 = fmaf(h, w.z, a2);
            a3 = fmaf(h, w.w, a3);
        }
    }
#pragma unroll
    for (int off = 16; off; off >>= 1) {
        a0 += __shfl_xor_sync(0xffffffffu, a0, off);
        a1 += __shfl_xor_sync(0xffffffffu, a1, off);
        a2 += __shfl_xor_sync(0xffffffffu, a2, off);
        a3 += __shfl_xor_sync(0xffffffffu, a3, off);
    }
    __shared__ float s[8][4];
    if ((t & 31) == 0) {
        int w = t >> 5;
        s[w][0] = a0; s[w][1] = a1; s[w][2] = a2; s[w][3] = a3;
    }
    __syncthreads();
    if (t < 4) {
        float r = 0.f;
#pragma unroll
        for (int w = 0; w < 8; w++) r += s[w][t];
        out[b * 4 + t] = r + b2[t];
    }
}

// ---------------------------------------------------------------------------
extern "C" void kernel_launch(void* const* d_in, const int* in_sizes, int n_in,
                              void* d_out, int out_size) {
    const float* x  = (const float*)d_in[0];
    const int*   nf = (const int*)  d_in[1];
    const float* q  = (const float*)d_in[2];
    const float* W1 = (const float*)d_in[3];
    const float* b1 = (const float*)d_in[4];
    const float* W2 = (const float*)d_in[5];
    const float* b2 = (const float*)d_in[6];

    float* out_p  = (float*)d_out;              // (B, 4) = 128 floats
    float* attn_p = out_p + Bz * Oo;            // (O, F, B, H) = 1,048,576 floats

    const int smemA = (64 * 67 + 8 * 1056) * 4; // 50944 B
    cudaFuncSetAttribute(k_logits, cudaFuncAttributeMaxDynamicSharedMemorySize, smemA);
    const int smemG = (2 * 32 * AP + 2 * 16 * WP) * 4;  // 83968 B
    cudaFuncSetAttribute(k_gemm1, cudaFuncAttributeMaxDynamicSharedMemorySize, smemG);

    dim3 gA(Bz, Ff / 8);
    k_logits<<<gA, 512, smemA>>>(x, nf, q);

    k_softmax<<<Oo * Bz, 256>>>(attn_p);

    dim3 gC(Bz, CH);
    k_wsum<<<gC, 1024>>>(x, nf, attn_p);

    k_csum<<<(Bz * FC) / 256, 256>>>();         // 4th launch (ncu)

    dim3 gD(FC / 128, NK);
    k_gemm1<<<gD, 256, smemG>>>(W1);

    k_hsum<<<(Bz * FC) / 256, 256>>>(b1);

    k_out<<<Bz, 256>>>(W2, b2, out_p);
}

// round 13
// speedup vs baseline: 1.4290x; 1.0653x over previous
#include <cuda_runtime.h>
#include <cstdint>
#include <cstddef>

#define Bz 32
#define Dd 1024
#define Ff 512
#define Hh 16
#define Oo 4
#define FC 4096
#define CH 16           // wsum chunks
#define FL 32           // frames per chunk
#define NK 16           // gemm k-splits (k-chunk 256)

// Deterministic scratch (no device allocation allowed)
__device__ float g_logits[Oo * Bz * Hh * Ff];        // [o][b][h][f]  4 MB
__device__ float g_hcat_part[CH * Bz * FC];          // [chunk][b][o*1024+d] 8 MB
__device__ float g_hcat[Bz * FC];                    // [b][o*1024+d]  512 KB
__device__ float g_hidden_part[NK * Bz * FC];        // [kblk][b][j]  8 MB
__device__ float g_out_part[Bz * 8 * 4];             // [b][jc][n]
__device__ float g_dummy;

__global__ void k_dummy() { g_dummy = 1.0f; }

// ---------------------------------------------------------------------------
// Kernel A: logits[o,b,h,f] = (x[f,b,h,:] . q[o,h,:]) / 8, masked to -50
// ---------------------------------------------------------------------------
__global__ void k_logits(const float* __restrict__ x, const int* __restrict__ nfp,
                         const float* __restrict__ q) {
    extern __shared__ float sm[];
    float* qs = sm;                 // 64 * 67
    float* xs = sm + 64 * 67;       // 8 * (16*66) = 8 * 1056
    int b  = blockIdx.x;
    int f0 = blockIdx.y * 8;
    int t  = threadIdx.x;
    int nf = nfp[b];

    for (int i = t; i < 64 * 64; i += 512)
        qs[(i >> 6) * 67 + (i & 63)] = q[i];

    for (int i = t; i < 8 * 512; i += 512) {
        int ff = i >> 9, j2 = i & 511;
        if (f0 + ff < nf) {
            int j = j2 * 2;
            float2 v = *(const float2*)&x[((size_t)(f0 + ff) * Bz + b) * Dd + j];
            *(float2*)&xs[ff * 1056 + (j >> 6) * 66 + (j & 63)] = v;
        }
    }
    __syncthreads();

    int fl = t >> 6;
    int oh = t & 63;
    int o = oh >> 4, h = oh & 15;
    int f = f0 + fl;

    float acc;
    if (f >= nf) {
        acc = -50.0f;
    } else {
        const float* xp = xs + fl * 1056 + h * 66;
        const float* qp = qs + oh * 67;
        float a = 0.f;
#pragma unroll
        for (int s = 0; s < 64; s++) a = fmaf(xp[s], qp[s], a);
        acc = a * 0.125f;
    }
    g_logits[((size_t)(o * Bz + b) * Hh + h) * Ff + f] = acc;
}

// ---------------------------------------------------------------------------
// Kernel B: softmax. 256 blocks (4o x 32b x 2 h-groups), warp-per-h,
// register-resident rows, smem transpose for 32B-chunk coalesced writes.
// ---------------------------------------------------------------------------
__global__ void k_softmax(float* __restrict__ attn) {
    int bid = blockIdx.x;            // 256
    int o = bid >> 6;
    int b = (bid >> 1) & 31;
    int hg = bid & 1;
    int t = threadIdx.x;             // 256
    int w = t >> 5, lane = t & 31;
    int h = hg * 8 + w;

    __shared__ float ps[8 * 524];

    const float* src = g_logits + ((size_t)(o * Bz + b) * Hh + h) * Ff;
    float v[16];
    float m = -1e30f;
#pragma unroll
    for (int i = 0; i < 16; i++) {
        v[i] = src[lane + i * 32];
        m = fmaxf(m, v[i]);
    }
#pragma unroll
    for (int off = 16; off; off >>= 1)
        m = fmaxf(m, __shfl_xor_sync(0xffffffffu, m, off));
    float s = 0.f;
#pragma unroll
    for (int i = 0; i < 16; i++) {
        v[i] = __expf(v[i] - m);
        s += v[i];
    }
#pragma unroll
    for (int off = 16; off; off >>= 1)
        s += __shfl_xor_sync(0xffffffffu, s, off);
    float inv = 1.0f / s;
#pragma unroll
    for (int i = 0; i < 16; i++)
        ps[w * 524 + lane + i * 32] = v[i] * inv;
    __syncthreads();

    float* dst = attn + (size_t)o * (Ff * Bz * Hh) + b * Hh + hg * 8;
    for (int i = t; i < 4096; i += 256) {
        int f = i >> 3, hl = i & 7;
        dst[(size_t)f * (Bz * Hh) + hl] = ps[hl * 524 + f];
    }
}

// ---------------------------------------------------------------------------
// Kernel C: partial weighted sums, 16 chunks x 32 frames (unroll 16).
// ---------------------------------------------------------------------------
__global__ void k_wsum(const float* __restrict__ x, const int* __restrict__ nfp,
                       const float* __restrict__ attn) {
    int b = blockIdx.x;
    int c = blockIdx.y;
    int f0 = c * FL;
    int nf = nfp[b];
    int d = threadIdx.x;
    int h = d >> 6;

    __shared__ float as[Oo * FL * Hh];   // [o][fl][h] 8 KB
    float a0 = 0.f, a1 = 0.f, a2 = 0.f, a3 = 0.f;

    if (f0 < nf) {
        for (int i = d; i < Oo * FL * Hh; i += 1024) {
            int o = i >> 9, r = i & 511;
            as[i] = attn[(size_t)o * (Ff * Bz * Hh) +
                         (size_t)(f0 + (r >> 4)) * (Bz * Hh) + b * Hh + (r & 15)];
        }
        __syncthreads();
        int fe = min(FL, nf - f0);
        const float* xp = x + ((size_t)f0 * Bz + b) * Dd + d;
        if (fe == FL) {
#pragma unroll 16
            for (int fl = 0; fl < FL; fl++) {
                float xv = xp[(size_t)fl * (Bz * Dd)];
                int ai = fl * 16 + h;
                a0 = fmaf(xv, as[ai],       a0);
                a1 = fmaf(xv, as[512 + ai], a1);
                a2 = fmaf(xv, as[1024 + ai], a2);
                a3 = fmaf(xv, as[1536 + ai], a3);
            }
        } else {
            for (int fl = 0; fl < fe; fl++) {
                float xv = xp[(size_t)fl * (Bz * Dd)];
                int ai = fl * 16 + h;
                a0 = fmaf(xv, as[ai],       a0);
                a1 = fmaf(xv, as[512 + ai], a1);
                a2 = fmaf(xv, as[1024 + ai], a2);
                a3 = fmaf(xv, as[1536 + ai], a3);
            }
        }
    }
    float* p = g_hcat_part + ((size_t)c * Bz + b) * FC + d;
    p[0] = a0; p[1024] = a1; p[2048] = a2; p[3072] = a3;
}

// Reduce 16 chunk partials into hcat. Scalar, 512 blocks, full-chip.
__global__ void k_csum() {
    int i = blockIdx.x * 256 + threadIdx.x;
    float s = 0.f;
#pragma unroll
    for (int c = 0; c < CH; c++) s += g_hcat_part[(size_t)c * (Bz * FC) + i];
    g_hcat[i] = s;
}

// ---------------------------------------------------------------------------
// Kernel D: 3xTF32 tensor-core GEMM, cp.async 3-stage W1 pipeline.
// ---------------------------------------------------------------------------
#define AP 260
#define WP 136
#define WSTG (16 * WP)

__device__ __forceinline__ uint32_t f2tf32(float x) {
    uint32_t r;
    asm("cvt.rna.tf32.f32 %0, %1;" : "=r"(r) : "f"(x));
    return r;
}

__device__ __forceinline__ void mma_tf32(float* d, const uint32_t* a,
                                         uint32_t b0, uint32_t b1) {
    asm("mma.sync.aligned.m16n8k8.row.col.f32.tf32.tf32.f32 "
        "{%0,%1,%2,%3}, {%4,%5,%6,%7}, {%8,%9}, {%0,%1,%2,%3};"
        : "+f"(d[0]), "+f"(d[1]), "+f"(d[2]), "+f"(d[3])
        : "r"(a[0]), "r"(a[1]), "r"(a[2]), "r"(a[3]), "r"(b0), "r"(b1));
}

__device__ __forceinline__ void cp16(float* dst, const float* src) {
    uint32_t d = (uint32_t)__cvta_generic_to_shared(dst);
    asm volatile("cp.async.cg.shared.global [%0], [%1], 16;"
                 :: "r"(d), "l"(src) : "memory");
}

__global__ void __launch_bounds__(256, 2) k_gemm1(const float* __restrict__ W1) {
    extern __shared__ float smg[];
    float* Ah = smg;                 // 32 * AP
    float* Al = Ah + 32 * AP;        // 32 * AP
    float* Ws = Al + 32 * AP;        // 3 * WSTG
    int t = threadIdx.x;
    int warp = t >> 5, lane = t & 31;
    int g = lane >> 2, tg = lane & 3;
    int jb = blockIdx.x * 128;
    int kb = blockIdx.y * 256;

    int wrow = t >> 5;
    int wcol = (t & 31) * 4;
    const float* wbase = W1 + (size_t)kb * FC + jb + wcol;

    // Kick off W stages 0 and 1 while A stages.
#pragma unroll
    for (int s = 0; s < 2; s++) {
        float* bb = Ws + s * WSTG;
        cp16(&bb[wrow * WP + wcol], wbase + (size_t)(s * 16 + wrow) * FC);
        cp16(&bb[(wrow + 8) * WP + wcol], wbase + (size_t)(s * 16 + wrow + 8) * FC);
        asm volatile("cp.async.commit_group;" ::: "memory");
    }

    // Stage A = hcat[0..31][kb..kb+255] as hi/lo tf32
    for (int idx = t; idx < 32 * 256; idx += 256) {
        int b = idx >> 8, c = idx & 255;
        float v = g_hcat[b * FC + kb + c];
        uint32_t hi = f2tf32(v);
        float lof = v - __uint_as_float(hi);
        Ah[b * AP + c] = __uint_as_float(hi);
        Al[b * AP + c] = __uint_as_float(f2tf32(lof));
    }

    float d[2][2][4];
#pragma unroll
    for (int mt = 0; mt < 2; mt++)
#pragma unroll
        for (int nt = 0; nt < 2; nt++)
#pragma unroll
            for (int e = 0; e < 4; e++) d[mt][nt][e] = 0.f;

    for (int ks = 0; ks < 16; ks++) {
        asm volatile("cp.async.wait_group 1;" ::: "memory");
        __syncthreads();                   // stage ks visible to all; buffers free

        // Issue stage ks+2 into buffer (ks+2)%3 (freed by compute ks-1).
        if (ks < 14) {
            float* bb = Ws + ((ks + 2) % 3) * WSTG;
            cp16(&bb[wrow * WP + wcol],
                 wbase + (size_t)((ks + 2) * 16 + wrow) * FC);
            cp16(&bb[(wrow + 8) * WP + wcol],
                 wbase + (size_t)((ks + 2) * 16 + wrow + 8) * FC);
        }
        asm volatile("cp.async.commit_group;" ::: "memory");

        const float* Wcur = Ws + (ks % 3) * WSTG;
#pragma unroll
        for (int sub = 0; sub < 2; sub++) {
            int ac = ks * 16 + sub * 8 + tg;
            uint32_t ah[2][4], al[2][4];
#pragma unroll
            for (int mt = 0; mt < 2; mt++) {
                int r0 = mt * 16 + g;
                ah[mt][0] = __float_as_uint(Ah[r0 * AP + ac]);
                ah[mt][1] = __float_as_uint(Ah[(r0 + 8) * AP + ac]);
                ah[mt][2] = __float_as_uint(Ah[r0 * AP + ac + 4]);
                ah[mt][3] = __float_as_uint(Ah[(r0 + 8) * AP + ac + 4]);
                al[mt][0] = __float_as_uint(Al[r0 * AP + ac]);
                al[mt][1] = __float_as_uint(Al[(r0 + 8) * AP + ac]);
                al[mt][2] = __float_as_uint(Al[r0 * AP + ac + 4]);
                al[mt][3] = __float_as_uint(Al[(r0 + 8) * AP + ac + 4]);
            }
#pragma unroll
            for (int nt = 0; nt < 2; nt++) {
                int jc = warp * 16 + nt * 8 + g;
                float b0f = Wcur[(sub * 8 + tg) * WP + jc];
                float b1f = Wcur[(sub * 8 + tg + 4) * WP + jc];
                uint32_t bh0 = f2tf32(b0f);
                uint32_t bl0 = f2tf32(b0f - __uint_as_float(bh0));
                uint32_t bh1 = f2tf32(b1f);
                uint32_t bl1 = f2tf32(b1f - __uint_as_float(bh1));
#pragma unroll
                for (int mt = 0; mt < 2; mt++) {
                    mma_tf32(d[mt][nt], ah[mt], bh0, bh1);
                    mma_tf32(d[mt][nt], al[mt], bh0, bh1);
                    mma_tf32(d[mt][nt], ah[mt], bl0, bl1);
                }
            }
        }
    }

    float* dst = g_hidden_part + (size_t)blockIdx.y * (Bz * FC);
#pragma unroll
    for (int mt = 0; mt < 2; mt++) {
#pragma unroll
        for (int nt = 0; nt < 2; nt++) {
            int j0 = jb + warp * 16 + nt * 8 + 2 * tg;
            int b0 = mt * 16 + g;
            *(float2*)&dst[(size_t)b0 * FC + j0] =
                make_float2(d[mt][nt][0], d[mt][nt][1]);
            *(float2*)&dst[(size_t)(b0 + 8) * FC + j0] =
                make_float2(d[mt][nt][2], d[mt][nt][3]);
        }
    }
}

// ---------------------------------------------------------------------------
// Kernel E1: fused slab-reduce + bias + ReLU + W2 partial dot.
// 256 blocks = 32 b x 8 j-chunks of 512. Partials to g_out_part.
// ---------------------------------------------------------------------------
__global__ void k_outp(const float* __restrict__ b1, const float* __restrict__ W2) {
    int bid = blockIdx.x;
    int b = bid >> 3, jc = bid & 7;
    int t = threadIdx.x;   // 256
    float a0 = 0.f, a1 = 0.f, a2 = 0.f, a3 = 0.f;

#pragma unroll
    for (int p = 0; p < 2; p++) {
        int j = jc * 512 + p * 256 + t;
        float s = b1[j];
#pragma unroll
        for (int kb = 0; kb < NK; kb++)
            s += g_hidden_part[(size_t)kb * (Bz * FC) + (size_t)b * FC + j];
        s = fmaxf(s, 0.f);
        float4 w = *(const float4*)(W2 + (size_t)j * 4);
        a0 = fmaf(s, w.x, a0);
        a1 = fmaf(s, w.y, a1);
        a2 = fmaf(s, w.z, a2);
        a3 = fmaf(s, w.w, a3);
    }
#pragma unroll
    for (int off = 16; off; off >>= 1) {
        a0 += __shfl_xor_sync(0xffffffffu, a0, off);
        a1 += __shfl_xor_sync(0xffffffffu, a1, off);
        a2 += __shfl_xor_sync(0xffffffffu, a2, off);
        a3 += __shfl_xor_sync(0xffffffffu, a3, off);
    }
    __shared__ float sred[8][4];
    if ((t & 31) == 0) {
        int w = t >> 5;
        sred[w][0] = a0; sred[w][1] = a1; sred[w][2] = a2; sred[w][3] = a3;
    }
    __syncthreads();
    if (t < 4) {
        float r = 0.f;
#pragma unroll
        for (int w = 0; w < 8; w++) r += sred[w][t];
        g_out_part[(b * 8 + jc) * 4 + t] = r;
    }
}

// Kernel E2: final reduce over 8 j-chunks.
__global__ void k_out2(const float* __restrict__ b2, float* __restrict__ out) {
    int i = threadIdx.x;      // 128 = 32 b x 4 n
    int b = i >> 2, n = i & 3;
    float r = b2[n];
#pragma unroll
    for (int jc = 0; jc < 8; jc++) r += g_out_part[(b * 8 + jc) * 4 + n];
    out[b * 4 + n] = r;
}

// ---------------------------------------------------------------------------
extern "C" void kernel_launch(void* const* d_in, const int* in_sizes, int n_in,
                              void* d_out, int out_size) {
    const float* x  = (const float*)d_in[0];
    const int*   nf = (const int*)  d_in[1];
    const float* q  = (const float*)d_in[2];
    const float* W1 = (const float*)d_in[3];
    const float* b1 = (const float*)d_in[4];
    const float* W2 = (const float*)d_in[5];
    const float* b2 = (const float*)d_in[6];

    float* out_p  = (float*)d_out;              // (B, 4) = 128 floats
    float* attn_p = out_p + Bz * Oo;            // (O, F, B, H) = 1,048,576 floats

    const int smemA = (64 * 67 + 8 * 1056) * 4; // 50944 B
    cudaFuncSetAttribute(k_logits, cudaFuncAttributeMaxDynamicSharedMemorySize, smemA);
    const int smemG = (2 * 32 * AP + 3 * WSTG) * 4;  // 92672 B
    cudaFuncSetAttribute(k_gemm1, cudaFuncAttributeMaxDynamicSharedMemorySize, smemG);

    k_dummy<<<1, 1>>>();
    k_dummy<<<1, 1>>>();
    k_dummy<<<1, 1>>>();                        // capture slot -> k_logits

    dim3 gA(Bz, Ff / 8);
    k_logits<<<gA, 512, smemA>>>(x, nf, q);     // 4th launch (ncu)

    k_softmax<<<256, 256>>>(attn_p);

    dim3 gC(Bz, CH);
    k_wsum<<<gC, 1024>>>(x, nf, attn_p);

    k_csum<<<(Bz * FC) / 256, 256>>>();

    dim3 gD(FC / 128, NK);
    k_gemm1<<<gD, 256, smemG>>>(W1);

    k_outp<<<Bz * 8, 256>>>(b1, W2);

    k_out2<<<1, 128>>>(b2, out_p);
}

// round 14
// speedup vs baseline: 1.5772x; 1.1037x over previous
#include <cuda_runtime.h>
#include <cstdint>
#include <cstddef>

#define Bz 32
#define Dd 1024
#define Ff 512
#define Hh 16
#define Oo 4
#define FC 4096
#define CH 16           // wsum chunks
#define FL 32           // frames per chunk
#define NK 16           // gemm k-splits (k-chunk 256)

// Deterministic scratch (no device allocation allowed)
__device__ float g_logits[Oo * Bz * Hh * Ff];        // [o][b][h][f]  4 MB
__device__ float g_hcat_part[CH * Bz * FC];          // [chunk][b][o*1024+d] 8 MB
__device__ float g_hcat[Bz * FC];                    // [b][o*1024+d]  512 KB
__device__ float g_hidden_part[NK * Bz * FC];        // [kblk][b][j]  8 MB
__device__ float g_out_part[Bz * 8 * 4];             // [b][jc][n]
__device__ float g_dummy;

__global__ void k_dummy() { g_dummy = 1.0f; }

// ---------------------------------------------------------------------------
// Kernel A: logits[o,b,h,f] = (x[f,b,h,:] . q[o,h,:]) / 8, masked to -50
// float4 smem: rows padded to 68 floats (17 float4) -> 16B-aligned rows,
// 17 mod 8 = 1 -> conflict-free LDS.128 per 8-lane phase for both arrays.
// Inner loop: 2 LDS.128 + 4 FMA (was 8 scalar LDS + 4 FMA in R13 = L1 44%).
// ---------------------------------------------------------------------------
__global__ void k_logits(const float* __restrict__ x, const int* __restrict__ nfp,
                         const float* __restrict__ q) {
    extern __shared__ float sm[];
    float4* qs4 = (float4*)sm;                  // 64 rows * 17 f4
    float4* xs4 = (float4*)(sm + 64 * 68);      // 8 * (16 * 17) f4
    int b  = blockIdx.x;
    int f0 = blockIdx.y * 8;
    int t  = threadIdx.x;
    int nf = nfp[b];

    // Stage q: 64 rows x 16 float4
    const float4* q4 = (const float4*)q;
    for (int i = t; i < 64 * 16; i += 512) {
        int row = i >> 4, s4 = i & 15;
        qs4[row * 17 + s4] = q4[row * 16 + s4];
    }

    // Stage x: 8 frames x 256 float4 (row (ff,h) at f4-offset ff*272 + h*17)
    const float4* x4 = (const float4*)x;
    for (int i = t; i < 8 * 256; i += 512) {
        int ff = i >> 8, j4 = i & 255;
        if (f0 + ff < nf) {
            int h = j4 >> 4, s4 = j4 & 15;
            xs4[ff * 272 + h * 17 + s4] =
                x4[((size_t)(f0 + ff) * Bz + b) * 256 + j4];
        }
    }
    __syncthreads();

    int fl = t >> 6;
    int oh = t & 63;
    int o = oh >> 4, h = oh & 15;
    int f = f0 + fl;

    float acc;
    if (f >= nf) {
        acc = -50.0f;
    } else {
        const float4* xp = xs4 + fl * 272 + h * 17;
        const float4* qp = qs4 + oh * 17;
        float a = 0.f;
#pragma unroll
        for (int s4 = 0; s4 < 16; s4++) {
            float4 xv = xp[s4];
            float4 qv = qp[s4];
            a = fmaf(xv.x, qv.x, a);
            a = fmaf(xv.y, qv.y, a);
            a = fmaf(xv.z, qv.z, a);
            a = fmaf(xv.w, qv.w, a);
        }
        acc = a * 0.125f;
    }
    g_logits[((size_t)(o * Bz + b) * Hh + h) * Ff + f] = acc;
}

// ---------------------------------------------------------------------------
// Kernel B: softmax. 256 blocks (4o x 32b x 2 h-groups), warp-per-h,
// register-resident rows, smem transpose for coalesced writes.
// ---------------------------------------------------------------------------
__global__ void k_softmax(float* __restrict__ attn) {
    int bid = blockIdx.x;            // 256
    int o = bid >> 6;
    int b = (bid >> 1) & 31;
    int hg = bid & 1;
    int t = threadIdx.x;             // 256
    int w = t >> 5, lane = t & 31;
    int h = hg * 8 + w;

    __shared__ float ps[8 * 524];

    const float* src = g_logits + ((size_t)(o * Bz + b) * Hh + h) * Ff;
    float v[16];
    float m = -1e30f;
#pragma unroll
    for (int i = 0; i < 16; i++) {
        v[i] = src[lane + i * 32];
        m = fmaxf(m, v[i]);
    }
#pragma unroll
    for (int off = 16; off; off >>= 1)
        m = fmaxf(m, __shfl_xor_sync(0xffffffffu, m, off));
    float s = 0.f;
#pragma unroll
    for (int i = 0; i < 16; i++) {
        v[i] = __expf(v[i] - m);
        s += v[i];
    }
#pragma unroll
    for (int off = 16; off; off >>= 1)
        s += __shfl_xor_sync(0xffffffffu, s, off);
    float inv = 1.0f / s;
#pragma unroll
    for (int i = 0; i < 16; i++)
        ps[w * 524 + lane + i * 32] = v[i] * inv;
    __syncthreads();

    float* dst = attn + (size_t)o * (Ff * Bz * Hh) + b * Hh + hg * 8;
    for (int i = t; i < 4096; i += 256) {
        int f = i >> 3, hl = i & 7;
        dst[(size_t)f * (Bz * Hh) + hl] = ps[hl * 524 + f];
    }
}

// ---------------------------------------------------------------------------
// Kernel C: partial weighted sums, 16 chunks x 32 frames (unroll 16).
// ---------------------------------------------------------------------------
__global__ void k_wsum(const float* __restrict__ x, const int* __restrict__ nfp,
                       const float* __restrict__ attn) {
    int b = blockIdx.x;
    int c = blockIdx.y;
    int f0 = c * FL;
    int nf = nfp[b];
    int d = threadIdx.x;
    int h = d >> 6;

    __shared__ float as[Oo * FL * Hh];   // [o][fl][h] 8 KB
    float a0 = 0.f, a1 = 0.f, a2 = 0.f, a3 = 0.f;

    if (f0 < nf) {
        for (int i = d; i < Oo * FL * Hh; i += 1024) {
            int o = i >> 9, r = i & 511;
            as[i] = attn[(size_t)o * (Ff * Bz * Hh) +
                         (size_t)(f0 + (r >> 4)) * (Bz * Hh) + b * Hh + (r & 15)];
        }
        __syncthreads();
        int fe = min(FL, nf - f0);
        const float* xp = x + ((size_t)f0 * Bz + b) * Dd + d;
        if (fe == FL) {
#pragma unroll 16
            for (int fl = 0; fl < FL; fl++) {
                float xv = xp[(size_t)fl * (Bz * Dd)];
                int ai = fl * 16 + h;
                a0 = fmaf(xv, as[ai],       a0);
                a1 = fmaf(xv, as[512 + ai], a1);
                a2 = fmaf(xv, as[1024 + ai], a2);
                a3 = fmaf(xv, as[1536 + ai], a3);
            }
        } else {
            for (int fl = 0; fl < fe; fl++) {
                float xv = xp[(size_t)fl * (Bz * Dd)];
                int ai = fl * 16 + h;
                a0 = fmaf(xv, as[ai],       a0);
                a1 = fmaf(xv, as[512 + ai], a1);
                a2 = fmaf(xv, as[1024 + ai], a2);
                a3 = fmaf(xv, as[1536 + ai], a3);
            }
        }
    }
    float* p = g_hcat_part + ((size_t)c * Bz + b) * FC + d;
    p[0] = a0; p[1024] = a1; p[2048] = a2; p[3072] = a3;
}

// Reduce 16 chunk partials into hcat. Scalar, 512 blocks, full-chip.
__global__ void k_csum() {
    int i = blockIdx.x * 256 + threadIdx.x;
    float s = 0.f;
#pragma unroll
    for (int c = 0; c < CH; c++) s += g_hcat_part[(size_t)c * (Bz * FC) + i];
    g_hcat[i] = s;
}

// ---------------------------------------------------------------------------
// Kernel D: 3xTF32 tensor-core GEMM, cp.async 3-stage W1 pipeline.
// ---------------------------------------------------------------------------
#define AP 260
#define WP 136
#define WSTG (16 * WP)

__device__ __forceinline__ uint32_t f2tf32(float x) {
    uint32_t r;
    asm("cvt.rna.tf32.f32 %0, %1;" : "=r"(r) : "f"(x));
    return r;
}

__device__ __forceinline__ void mma_tf32(float* d, const uint32_t* a,
                                         uint32_t b0, uint32_t b1) {
    asm("mma.sync.aligned.m16n8k8.row.col.f32.tf32.tf32.f32 "
        "{%0,%1,%2,%3}, {%4,%5,%6,%7}, {%8,%9}, {%0,%1,%2,%3};"
        : "+f"(d[0]), "+f"(d[1]), "+f"(d[2]), "+f"(d[3])
        : "r"(a[0]), "r"(a[1]), "r"(a[2]), "r"(a[3]), "r"(b0), "r"(b1));
}

__device__ __forceinline__ void cp16(float* dst, const float* src) {
    uint32_t d = (uint32_t)__cvta_generic_to_shared(dst);
    asm volatile("cp.async.cg.shared.global [%0], [%1], 16;"
                 :: "r"(d), "l"(src) : "memory");
}

__global__ void __launch_bounds__(256, 2) k_gemm1(const float* __restrict__ W1) {
    extern __shared__ float smg[];
    float* Ah = smg;                 // 32 * AP
    float* Al = Ah + 32 * AP;        // 32 * AP
    float* Ws = Al + 32 * AP;        // 3 * WSTG
    int t = threadIdx.x;
    int warp = t >> 5, lane = t & 31;
    int g = lane >> 2, tg = lane & 3;
    int jb = blockIdx.x * 128;
    int kb = blockIdx.y * 256;

    int wrow = t >> 5;
    int wcol = (t & 31) * 4;
    const float* wbase = W1 + (size_t)kb * FC + jb + wcol;

#pragma unroll
    for (int s = 0; s < 2; s++) {
        float* bb = Ws + s * WSTG;
        cp16(&bb[wrow * WP + wcol], wbase + (size_t)(s * 16 + wrow) * FC);
        cp16(&bb[(wrow + 8) * WP + wcol], wbase + (size_t)(s * 16 + wrow + 8) * FC);
        asm volatile("cp.async.commit_group;" ::: "memory");
    }

    for (int idx = t; idx < 32 * 256; idx += 256) {
        int b = idx >> 8, c = idx & 255;
        float v = g_hcat[b * FC + kb + c];
        uint32_t hi = f2tf32(v);
        float lof = v - __uint_as_float(hi);
        Ah[b * AP + c] = __uint_as_float(hi);
        Al[b * AP + c] = __uint_as_float(f2tf32(lof));
    }

    float d[2][2][4];
#pragma unroll
    for (int mt = 0; mt < 2; mt++)
#pragma unroll
        for (int nt = 0; nt < 2; nt++)
#pragma unroll
            for (int e = 0; e < 4; e++) d[mt][nt][e] = 0.f;

    for (int ks = 0; ks < 16; ks++) {
        asm volatile("cp.async.wait_group 1;" ::: "memory");
        __syncthreads();

        if (ks < 14) {
            float* bb = Ws + ((ks + 2) % 3) * WSTG;
            cp16(&bb[wrow * WP + wcol],
                 wbase + (size_t)((ks + 2) * 16 + wrow) * FC);
            cp16(&bb[(wrow + 8) * WP + wcol],
                 wbase + (size_t)((ks + 2) * 16 + wrow + 8) * FC);
        }
        asm volatile("cp.async.commit_group;" ::: "memory");

        const float* Wcur = Ws + (ks % 3) * WSTG;
#pragma unroll
        for (int sub = 0; sub < 2; sub++) {
            int ac = ks * 16 + sub * 8 + tg;
            uint32_t ah[2][4], al[2][4];
#pragma unroll
            for (int mt = 0; mt < 2; mt++) {
                int r0 = mt * 16 + g;
                ah[mt][0] = __float_as_uint(Ah[r0 * AP + ac]);
                ah[mt][1] = __float_as_uint(Ah[(r0 + 8) * AP + ac]);
                ah[mt][2] = __float_as_uint(Ah[r0 * AP + ac + 4]);
                ah[mt][3] = __float_as_uint(Ah[(r0 + 8) * AP + ac + 4]);
                al[mt][0] = __float_as_uint(Al[r0 * AP + ac]);
                al[mt][1] = __float_as_uint(Al[(r0 + 8) * AP + ac]);
                al[mt][2] = __float_as_uint(Al[r0 * AP + ac + 4]);
                al[mt][3] = __float_as_uint(Al[(r0 + 8) * AP + ac + 4]);
            }
#pragma unroll
            for (int nt = 0; nt < 2; nt++) {
                int jc = warp * 16 + nt * 8 + g;
                float b0f = Wcur[(sub * 8 + tg) * WP + jc];
                float b1f = Wcur[(sub * 8 + tg + 4) * WP + jc];
                uint32_t bh0 = f2tf32(b0f);
                uint32_t bl0 = f2tf32(b0f - __uint_as_float(bh0));
                uint32_t bh1 = f2tf32(b1f);
                uint32_t bl1 = f2tf32(b1f - __uint_as_float(bh1));
#pragma unroll
                for (int mt = 0; mt < 2; mt++) {
                    mma_tf32(d[mt][nt], ah[mt], bh0, bh1);
                    mma_tf32(d[mt][nt], al[mt], bh0, bh1);
                    mma_tf32(d[mt][nt], ah[mt], bl0, bl1);
                }
            }
        }
    }

    float* dst = g_hidden_part + (size_t)blockIdx.y * (Bz * FC);
#pragma unroll
    for (int mt = 0; mt < 2; mt++) {
#pragma unroll
        for (int nt = 0; nt < 2; nt++) {
            int j0 = jb + warp * 16 + nt * 8 + 2 * tg;
            int b0 = mt * 16 + g;
            *(float2*)&dst[(size_t)b0 * FC + j0] =
                make_float2(d[mt][nt][0], d[mt][nt][1]);
            *(float2*)&dst[(size_t)(b0 + 8) * FC + j0] =
                make_float2(d[mt][nt][2], d[mt][nt][3]);
        }
    }
}

// ---------------------------------------------------------------------------
// Kernel E1: fused slab-reduce + bias + ReLU + W2 partial dot.
// 256 blocks = 32 b x 8 j-chunks of 512. Partials to g_out_part.
// ---------------------------------------------------------------------------
__global__ void k_outp(const float* __restrict__ b1, const float* __restrict__ W2) {
    int bid = blockIdx.x;
    int b = bid >> 3, jc = bid & 7;
    int t = threadIdx.x;   // 256
    float a0 = 0.f, a1 = 0.f, a2 = 0.f, a3 = 0.f;

#pragma unroll
    for (int p = 0; p < 2; p++) {
        int j = jc * 512 + p * 256 + t;
        float s = b1[j];
#pragma unroll
        for (int kb = 0; kb < NK; kb++)
            s += g_hidden_part[(size_t)kb * (Bz * FC) + (size_t)b * FC + j];
        s = fmaxf(s, 0.f);
        float4 w = *(const float4*)(W2 + (size_t)j * 4);
        a0 = fmaf(s, w.x, a0);
        a1 = fmaf(s, w.y, a1);
        a2 = fmaf(s, w.z, a2);
        a3 = fmaf(s, w.w, a3);
    }
#pragma unroll
    for (int off = 16; off; off >>= 1) {
        a0 += __shfl_xor_sync(0xffffffffu, a0, off);
        a1 += __shfl_xor_sync(0xffffffffu, a1, off);
        a2 += __shfl_xor_sync(0xffffffffu, a2, off);
        a3 += __shfl_xor_sync(0xffffffffu, a3, off);
    }
    __shared__ float sred[8][4];
    if ((t & 31) == 0) {
        int w = t >> 5;
        sred[w][0] = a0; sred[w][1] = a1; sred[w][2] = a2; sred[w][3] = a3;
    }
    __syncthreads();
    if (t < 4) {
        float r = 0.f;
#pragma unroll
        for (int w = 0; w < 8; w++) r += sred[w][t];
        g_out_part[(b * 8 + jc) * 4 + t] = r;
    }
}

// Kernel E2: final reduce over 8 j-chunks.
__global__ void k_out2(const float* __restrict__ b2, float* __restrict__ out) {
    int i = threadIdx.x;      // 128 = 32 b x 4 n
    int b = i >> 2, n = i & 3;
    float r = b2[n];
#pragma unroll
    for (int jc = 0; jc < 8; jc++) r += g_out_part[(b * 8 + jc) * 4 + n];
    out[b * 4 + n] = r;
}

// ---------------------------------------------------------------------------
extern "C" void kernel_launch(void* const* d_in, const int* in_sizes, int n_in,
                              void* d_out, int out_size) {
    const float* x  = (const float*)d_in[0];
    const int*   nf = (const int*)  d_in[1];
    const float* q  = (const float*)d_in[2];
    const float* W1 = (const float*)d_in[3];
    const float* b1 = (const float*)d_in[4];
    const float* W2 = (const float*)d_in[5];
    const float* b2 = (const float*)d_in[6];

    float* out_p  = (float*)d_out;              // (B, 4) = 128 floats
    float* attn_p = out_p + Bz * Oo;            // (O, F, B, H) = 1,048,576 floats

    const int smemA = (64 * 68 + 8 * 16 * 68) * 4;   // 52224 B
    cudaFuncSetAttribute(k_logits, cudaFuncAttributeMaxDynamicSharedMemorySize, smemA);
    const int smemG = (2 * 32 * AP + 3 * WSTG) * 4;  // 92672 B
    cudaFuncSetAttribute(k_gemm1, cudaFuncAttributeMaxDynamicSharedMemorySize, smemG);

    k_dummy<<<1, 1>>>();
    k_dummy<<<1, 1>>>();
    k_dummy<<<1, 1>>>();                        // capture slot -> k_logits

    dim3 gA(Bz, Ff / 8);
    k_logits<<<gA, 512, smemA>>>(x, nf, q);     // 4th launch (ncu)

    k_softmax<<<256, 256>>>(attn_p);

    dim3 gC(Bz, CH);
    k_wsum<<<gC, 1024>>>(x, nf, attn_p);

    k_csum<<<(Bz * FC) / 256, 256>>>();

    dim3 gD(FC / 128, NK);
    k_gemm1<<<gD, 256, smemG>>>(W1);

    k_outp<<<Bz * 8, 256>>>(b1, W2);

    k_out2<<<1, 128>>>(b2, out_p);
}

// round 16
// speedup vs baseline: 1.8140x; 1.1502x over previous
#include <cuda_runtime.h>
#include <cstdint>
#include <cstddef>

#define Bz 32
#define Dd 1024
#define Ff 512
#define Hh 16
#define Oo 4
#define FC 4096
#define CH 16           // wsum chunks
#define FL 32           // frames per chunk
#define NK 16           // gemm k-splits (k-chunk 256)

// Deterministic scratch (no device allocation allowed)
__device__ float g_logits[Oo * Bz * Hh * Ff];        // [o][b][h][f]  4 MB
__device__ float g_hcat_part[CH * Bz * FC];          // [chunk][b][o*1024+d] 8 MB
__device__ float g_hcat[Bz * FC];                    // [b][o*1024+d]  512 KB
__device__ float g_hidden_part[NK * Bz * FC];        // [kblk][b][j]  8 MB
__device__ float g_out_part[Bz * 8 * 4];             // [b][jc][n]

// ---------------------------------------------------------------------------
// Kernel A: logits[o,b,h,f] = (x[f,b,h,:] . q[o,h,:]) / 8, masked to -50
// No smem. Warp = (h, 8 frames); lane = (f, s-quarter). q in registers
// (4o x 16s per lane, loaded once). x via 4 LDG.128/lane/frame directly
// from gmem (sg-lanes form 256B contiguous runs -> full sectors).
// Shfl-reduce over the 4 s-quarter lanes. R14 was smem-BW-bound (L1 55%).
// ---------------------------------------------------------------------------
__global__ void __launch_bounds__(256) k_logits(const float* __restrict__ x,
                                                const int* __restrict__ nfp,
                                                const float* __restrict__ q) {
    int b  = blockIdx.x;
    int fg = blockIdx.y;             // 8 groups of 64 frames
    int hg = blockIdx.z;             // 2 h-groups
    int t = threadIdx.x;             // 256
    int w = t >> 5, lane = t & 31;
    int h = hg * 8 + w;
    int fl = lane >> 2, sg = lane & 3;
    int nf = nfp[b];

    // q[o][h][sg*16 .. +16) in registers: 16 float4 per lane (L2-resident).
    float4 qr[4][4];
    const float4* qbase = (const float4*)(q + h * 64 + sg * 16);
#pragma unroll
    for (int o = 0; o < 4; o++)
#pragma unroll
        for (int i = 0; i < 4; i++)
            qr[o][i] = qbase[o * 256 + i];

    for (int ft = 0; ft < 8; ft++) {
        int fbase = fg * 64 + ft * 8;
        int f = fbase + fl;
        float a0 = 0.f, a1 = 0.f, a2 = 0.f, a3 = 0.f;
        if (fbase < nf) {            // block-uniform guard
            const float4* xp = (const float4*)
                (x + ((size_t)f * Bz + b) * Dd + h * 64 + sg * 16);
            float4 xr[4];
#pragma unroll
            for (int i = 0; i < 4; i++) xr[i] = xp[i];
#pragma unroll
            for (int i = 0; i < 4; i++) {
                a0 = fmaf(xr[i].x, qr[0][i].x, a0);
                a0 = fmaf(xr[i].y, qr[0][i].y, a0);
                a0 = fmaf(xr[i].z, qr[0][i].z, a0);
                a0 = fmaf(xr[i].w, qr[0][i].w, a0);
                a1 = fmaf(xr[i].x, qr[1][i].x, a1);
                a1 = fmaf(xr[i].y, qr[1][i].y, a1);
                a1 = fmaf(xr[i].z, qr[1][i].z, a1);
                a1 = fmaf(xr[i].w, qr[1][i].w, a1);
                a2 = fmaf(xr[i].x, qr[2][i].x, a2);
                a2 = fmaf(xr[i].y, qr[2][i].y, a2);
                a2 = fmaf(xr[i].z, qr[2][i].z, a2);
                a2 = fmaf(xr[i].w, qr[2][i].w, a2);
                a3 = fmaf(xr[i].x, qr[3][i].x, a3);
                a3 = fmaf(xr[i].y, qr[3][i].y, a3);
                a3 = fmaf(xr[i].z, qr[3][i].z, a3);
                a3 = fmaf(xr[i].w, qr[3][i].w, a3);
            }
        }
        // Reduce over the 4 s-quarter lanes (sg = low 2 bits of lane).
        a0 += __shfl_xor_sync(0xffffffffu, a0, 1);
        a0 += __shfl_xor_sync(0xffffffffu, a0, 2);
        a1 += __shfl_xor_sync(0xffffffffu, a1, 1);
        a1 += __shfl_xor_sync(0xffffffffu, a1, 2);
        a2 += __shfl_xor_sync(0xffffffffu, a2, 1);
        a2 += __shfl_xor_sync(0xffffffffu, a2, 2);
        a3 += __shfl_xor_sync(0xffffffffu, a3, 1);
        a3 += __shfl_xor_sync(0xffffffffu, a3, 2);
        if (sg == 0) {
            bool valid = f < nf;
            size_t base = ((size_t)b * Hh + h) * Ff + f;
            g_logits[base]                      = valid ? a0 * 0.125f : -50.0f;
            g_logits[base + (size_t)Bz*Hh*Ff]   = valid ? a1 * 0.125f : -50.0f;
            g_logits[base + (size_t)2*Bz*Hh*Ff] = valid ? a2 * 0.125f : -50.0f;
            g_logits[base + (size_t)3*Bz*Hh*Ff] = valid ? a3 * 0.125f : -50.0f;
        }
    }
}

// ---------------------------------------------------------------------------
// Kernel B: softmax. 256 blocks (4o x 32b x 2 h-groups), warp-per-h,
// register-resident rows, smem transpose for coalesced writes.
// ---------------------------------------------------------------------------
__global__ void k_softmax(float* __restrict__ attn) {
    int bid = blockIdx.x;            // 256
    int o = bid >> 6;
    int b = (bid >> 1) & 31;
    int hg = bid & 1;
    int t = threadIdx.x;             // 256
    int w = t >> 5, lane = t & 31;
    int h = hg * 8 + w;

    __shared__ float ps[8 * 524];

    const float* src = g_logits + ((size_t)(o * Bz + b) * Hh + h) * Ff;
    float v[16];
    float m = -1e30f;
#pragma unroll
    for (int i = 0; i < 16; i++) {
        v[i] = src[lane + i * 32];
        m = fmaxf(m, v[i]);
    }
#pragma unroll
    for (int off = 16; off; off >>= 1)
        m = fmaxf(m, __shfl_xor_sync(0xffffffffu, m, off));
    float s = 0.f;
#pragma unroll
    for (int i = 0; i < 16; i++) {
        v[i] = __expf(v[i] - m);
        s += v[i];
    }
#pragma unroll
    for (int off = 16; off; off >>= 1)
        s += __shfl_xor_sync(0xffffffffu, s, off);
    float inv = 1.0f / s;
#pragma unroll
    for (int i = 0; i < 16; i++)
        ps[w * 524 + lane + i * 32] = v[i] * inv;
    __syncthreads();

    float* dst = attn + (size_t)o * (Ff * Bz * Hh) + b * Hh + hg * 8;
    for (int i = t; i < 4096; i += 256) {
        int f = i >> 3, hl = i & 7;
        dst[(size_t)f * (Bz * Hh) + hl] = ps[hl * 524 + f];
    }
}

// ---------------------------------------------------------------------------
// Kernel C: partial weighted sums, 16 chunks x 32 frames (unroll 16).
// ---------------------------------------------------------------------------
__global__ void k_wsum(const float* __restrict__ x, const int* __restrict__ nfp,
                       const float* __restrict__ attn) {
    int b = blockIdx.x;
    int c = blockIdx.y;
    int f0 = c * FL;
    int nf = nfp[b];
    int d = threadIdx.x;
    int h = d >> 6;

    __shared__ float as[Oo * FL * Hh];   // [o][fl][h] 8 KB
    float a0 = 0.f, a1 = 0.f, a2 = 0.f, a3 = 0.f;

    if (f0 < nf) {
        for (int i = d; i < Oo * FL * Hh; i += 1024) {
            int o = i >> 9, r = i & 511;
            as[i] = attn[(size_t)o * (Ff * Bz * Hh) +
                         (size_t)(f0 + (r >> 4)) * (Bz * Hh) + b * Hh + (r & 15)];
        }
        __syncthreads();
        int fe = min(FL, nf - f0);
        const float* xp = x + ((size_t)f0 * Bz + b) * Dd + d;
        if (fe == FL) {
#pragma unroll 16
            for (int fl = 0; fl < FL; fl++) {
                float xv = xp[(size_t)fl * (Bz * Dd)];
                int ai = fl * 16 + h;
                a0 = fmaf(xv, as[ai],       a0);
                a1 = fmaf(xv, as[512 + ai], a1);
                a2 = fmaf(xv, as[1024 + ai], a2);
                a3 = fmaf(xv, as[1536 + ai], a3);
            }
        } else {
            for (int fl = 0; fl < fe; fl++) {
                float xv = xp[(size_t)fl * (Bz * Dd)];
                int ai = fl * 16 + h;
                a0 = fmaf(xv, as[ai],       a0);
                a1 = fmaf(xv, as[512 + ai], a1);
                a2 = fmaf(xv, as[1024 + ai], a2);
                a3 = fmaf(xv, as[1536 + ai], a3);
            }
        }
    }
    float* p = g_hcat_part + ((size_t)c * Bz + b) * FC + d;
    p[0] = a0; p[1024] = a1; p[2048] = a2; p[3072] = a3;
}

// Reduce 16 chunk partials into hcat. Scalar, 512 blocks, full-chip.
__global__ void k_csum() {
    int i = blockIdx.x * 256 + threadIdx.x;
    float s = 0.f;
#pragma unroll
    for (int c = 0; c < CH; c++) s += g_hcat_part[(size_t)c * (Bz * FC) + i];
    g_hcat[i] = s;
}

// ---------------------------------------------------------------------------
// Kernel D: 3xTF32 tensor-core GEMM, cp.async 3-stage W1 pipeline.
// ---------------------------------------------------------------------------
#define AP 260
#define WP 136
#define WSTG (16 * WP)

__device__ __forceinline__ uint32_t f2tf32(float x) {
    uint32_t r;
    asm("cvt.rna.tf32.f32 %0, %1;" : "=r"(r) : "f"(x));
    return r;
}

__device__ __forceinline__ void mma_tf32(float* d, const uint32_t* a,
                                         uint32_t b0, uint32_t b1) {
    asm("mma.sync.aligned.m16n8k8.row.col.f32.tf32.tf32.f32 "
        "{%0,%1,%2,%3}, {%4,%5,%6,%7}, {%8,%9}, {%0,%1,%2,%3};"
        : "+f"(d[0]), "+f"(d[1]), "+f"(d[2]), "+f"(d[3])
        : "r"(a[0]), "r"(a[1]), "r"(a[2]), "r"(a[3]), "r"(b0), "r"(b1));
}

__device__ __forceinline__ void cp16(float* dst, const float* src) {
    uint32_t d = (uint32_t)__cvta_generic_to_shared(dst);
    asm volatile("cp.async.cg.shared.global [%0], [%1], 16;"
                 :: "r"(d), "l"(src) : "memory");
}

__global__ void __launch_bounds__(256, 2) k_gemm1(const float* __restrict__ W1) {
    extern __shared__ float smg[];
    float* Ah = smg;                 // 32 * AP
    float* Al = Ah + 32 * AP;        // 32 * AP
    float* Ws = Al + 32 * AP;        // 3 * WSTG
    int t = threadIdx.x;
    int warp = t >> 5, lane = t & 31;
    int g = lane >> 2, tg = lane & 3;
    int jb = blockIdx.x * 128;
    int kb = blockIdx.y * 256;

    int wrow = t >> 5;
    int wcol = (t & 31) * 4;
    const float* wbase = W1 + (size_t)kb * FC + jb + wcol;

#pragma unroll
    for (int s = 0; s < 2; s++) {
        float* bb = Ws + s * WSTG;
        cp16(&bb[wrow * WP + wcol], wbase + (size_t)(s * 16 + wrow) * FC);
        cp16(&bb[(wrow + 8) * WP + wcol], wbase + (size_t)(s * 16 + wrow + 8) * FC);
        asm volatile("cp.async.commit_group;" ::: "memory");
    }

    for (int idx = t; idx < 32 * 256; idx += 256) {
        int b = idx >> 8, c = idx & 255;
        float v = g_hcat[b * FC + kb + c];
        uint32_t hi = f2tf32(v);
        float lof = v - __uint_as_float(hi);
        Ah[b * AP + c] = __uint_as_float(hi);
        Al[b * AP + c] = __uint_as_float(f2tf32(lof));
    }

    float d[2][2][4];
#pragma unroll
    for (int mt = 0; mt < 2; mt++)
#pragma unroll
        for (int nt = 0; nt < 2; nt++)
#pragma unroll
            for (int e = 0; e < 4; e++) d[mt][nt][e] = 0.f;

    for (int ks = 0; ks < 16; ks++) {
        asm volatile("cp.async.wait_group 1;" ::: "memory");
        __syncthreads();

        if (ks < 14) {
            float* bb = Ws + ((ks + 2) % 3) * WSTG;
            cp16(&bb[wrow * WP + wcol],
                 wbase + (size_t)((ks + 2) * 16 + wrow) * FC);
            cp16(&bb[(wrow + 8) * WP + wcol],
                 wbase + (size_t)((ks + 2) * 16 + wrow + 8) * FC);
        }
        asm volatile("cp.async.commit_group;" ::: "memory");

        const float* Wcur = Ws + (ks % 3) * WSTG;
#pragma unroll
        for (int sub = 0; sub < 2; sub++) {
            int ac = ks * 16 + sub * 8 + tg;
            uint32_t ah[2][4], al[2][4];
#pragma unroll
            for (int mt = 0; mt < 2; mt++) {
                int r0 = mt * 16 + g;
                ah[mt][0] = __float_as_uint(Ah[r0 * AP + ac]);
                ah[mt][1] = __float_as_uint(Ah[(r0 + 8) * AP + ac]);
                ah[mt][2] = __float_as_uint(Ah[r0 * AP + ac + 4]);
                ah[mt][3] = __float_as_uint(Ah[(r0 + 8) * AP + ac + 4]);
                al[mt][0] = __float_as_uint(Al[r0 * AP + ac]);
                al[mt][1] = __float_as_uint(Al[(r0 + 8) * AP + ac]);
                al[mt][2] = __float_as_uint(Al[r0 * AP + ac + 4]);
                al[mt][3] = __float_as_uint(Al[(r0 + 8) * AP + ac + 4]);
            }
#pragma unroll
            for (int nt = 0; nt < 2; nt++) {
                int jc = warp * 16 + nt * 8 + g;
                float b0f = Wcur[(sub * 8 + tg) * WP + jc];
                float b1f = Wcur[(sub * 8 + tg + 4) * WP + jc];
                uint32_t bh0 = f2tf32(b0f);
                uint32_t bl0 = f2tf32(b0f - __uint_as_float(bh0));
                uint32_t bh1 = f2tf32(b1f);
                uint32_t bl1 = f2tf32(b1f - __uint_as_float(bh1));
#pragma unroll
                for (int mt = 0; mt < 2; mt++) {
                    mma_tf32(d[mt][nt], ah[mt], bh0, bh1);
                    mma_tf32(d[mt][nt], al[mt], bh0, bh1);
                    mma_tf32(d[mt][nt], ah[mt], bl0, bl1);
                }
            }
        }
    }

    float* dst = g_hidden_part + (size_t)blockIdx.y * (Bz * FC);
#pragma unroll
    for (int mt = 0; mt < 2; mt++) {
#pragma unroll
        for (int nt = 0; nt < 2; nt++) {
            int j0 = jb + warp * 16 + nt * 8 + 2 * tg;
            int b0 = mt * 16 + g;
            *(float2*)&dst[(size_t)b0 * FC + j0] =
                make_float2(d[mt][nt][0], d[mt][nt][1]);
            *(float2*)&dst[(size_t)(b0 + 8) * FC + j0] =
                make_float2(d[mt][nt][2], d[mt][nt][3]);
        }
    }
}

// ---------------------------------------------------------------------------
// Kernel E1: fused slab-reduce + bias + ReLU + W2 partial dot.
// 256 blocks = 32 b x 8 j-chunks of 512. Partials to g_out_part.
// ---------------------------------------------------------------------------
__global__ void k_outp(const float* __restrict__ b1, const float* __restrict__ W2) {
    int bid = blockIdx.x;
    int b = bid >> 3, jc = bid & 7;
    int t = threadIdx.x;   // 256
    float a0 = 0.f, a1 = 0.f, a2 = 0.f, a3 = 0.f;

#pragma unroll
    for (int p = 0; p < 2; p++) {
        int j = jc * 512 + p * 256 + t;
        float s = b1[j];
#pragma unroll
        for (int kb = 0; kb < NK; kb++)
            s += g_hidden_part[(size_t)kb * (Bz * FC) + (size_t)b * FC + j];
        s = fmaxf(s, 0.f);
        float4 w = *(const float4*)(W2 + (size_t)j * 4);
        a0 = fmaf(s, w.x, a0);
        a1 = fmaf(s, w.y, a1);
        a2 = fmaf(s, w.z, a2);
        a3 = fmaf(s, w.w, a3);
    }
#pragma unroll
    for (int off = 16; off; off >>= 1) {
        a0 += __shfl_xor_sync(0xffffffffu, a0, off);
        a1 += __shfl_xor_sync(0xffffffffu, a1, off);
        a2 += __shfl_xor_sync(0xffffffffu, a2, off);
        a3 += __shfl_xor_sync(0xffffffffu, a3, off);
    }
    __shared__ float sred[8][4];
    if ((t & 31) == 0) {
        int w = t >> 5;
        sred[w][0] = a0; sred[w][1] = a1; sred[w][2] = a2; sred[w][3] = a3;
    }
    __syncthreads();
    if (t < 4) {
        float r = 0.f;
#pragma unroll
        for (int w = 0; w < 8; w++) r += sred[w][t];
        g_out_part[(b * 8 + jc) * 4 + t] = r;
    }
}

// Kernel E2: final reduce over 8 j-chunks.
__global__ void k_out2(const float* __restrict__ b2, float* __restrict__ out) {
    int i = threadIdx.x;      // 128 = 32 b x 4 n
    int b = i >> 2, n = i & 3;
    float r = b2[n];
#pragma unroll
    for (int jc = 0; jc < 8; jc++) r += g_out_part[(b * 8 + jc) * 4 + n];
    out[b * 4 + n] = r;
}

// ---------------------------------------------------------------------------
extern "C" void kernel_launch(void* const* d_in, const int* in_sizes, int n_in,
                              void* d_out, int out_size) {
    const float* x  = (const float*)d_in[0];
    const int*   nf = (const int*)  d_in[1];
    const float* q  = (const float*)d_in[2];
    const float* W1 = (const float*)d_in[3];
    const float* b1 = (const float*)d_in[4];
    const float* W2 = (const float*)d_in[5];
    const float* b2 = (const float*)d_in[6];

    float* out_p  = (float*)d_out;              // (B, 4) = 128 floats
    float* attn_p = out_p + Bz * Oo;            // (O, F, B, H) = 1,048,576 floats

    const int smemG = (2 * 32 * AP + 3 * WSTG) * 4;  // 92672 B
    cudaFuncSetAttribute(k_gemm1, cudaFuncAttributeMaxDynamicSharedMemorySize, smemG);

    dim3 gA(Bz, 8, 2);
    k_logits<<<gA, 256>>>(x, nf, q);

    k_softmax<<<256, 256>>>(attn_p);

    dim3 gC(Bz, CH);
    k_wsum<<<gC, 1024>>>(x, nf, attn_p);

    k_csum<<<(Bz * FC) / 256, 256>>>();

    dim3 gD(FC / 128, NK);
    k_gemm1<<<gD, 256, smemG>>>(W1);

    k_outp<<<Bz * 8, 256>>>(b1, W2);

    k_out2<<<1, 128>>>(b2, out_p);
}